// round 2
// baseline (speedup 1.0000x reference)
#include <cuda_runtime.h>
#include <math.h>

#define BB 128
#define TT 256
#define DD 512
#define LL 1024
#define NB 128   // persistent grid size (<=148 SMs -> co-resident)

// ---------- scratch (static device memory; no allocations) ----------
__device__ __align__(16) float g_xz[TT * BB * LL];   // x @ Wz_x^T + bz, [t][b][l]
__device__ __align__(16) float g_xr[TT * BB * LL];
__device__ __align__(16) float g_xi[TT * BB * LL];
__device__ __align__(16) float g_h [BB * LL];        // current hidden
__device__ __align__(16) float g_z [BB * LL];        // update gate for current step
__device__ __align__(16) float g_rh[BB * LL];        // r * h for current step
__device__ __align__(16) float g_p1[8  * BB * 2048]; // K-split partials, phase 1
__device__ __align__(16) float g_p2[16 * BB * LL];   // K-split partials, phase 2
__device__ unsigned g_bar1 = 0;                      // grid barrier arrive counter
__device__ unsigned g_bar2 = 0;                      // exit confirmation counter

typedef unsigned long long ull;

__device__ __forceinline__ ull pack2(float v) {
    ull r; asm("mov.b64 %0, {%1, %1};" : "=l"(r) : "f"(v)); return r;
}
__device__ __forceinline__ void ffma2(ull& d, ull a, ull b) {
    asm("fma.rn.f32x2 %0, %1, %2, %0;" : "+l"(d) : "l"(a), "l"(b));
}
__device__ __forceinline__ float2 unpack2(ull v) {
    float2 f; asm("mov.b64 {%0, %1}, %2;" : "=f"(f.x), "=f"(f.y) : "l"(v)); return f;
}

// Software grid barrier: 128 CTAs, cumulative counter. Thread 0 arrives + spins.
__device__ __forceinline__ void grid_sync(unsigned target) {
    __syncthreads();
    if (threadIdx.x == 0) {
        __threadfence();
        atomicAdd(&g_bar1, 1u);
        unsigned v;
        do {
            asm volatile("ld.acquire.gpu.u32 %0, [%1];" : "=r"(v) : "l"(&g_bar1));
        } while (v < target);
    }
    __syncthreads();
}

// 128x128 tile, 16-deep K chunk, 256 threads, 8x8 micro-tile via f32x2 FFMA.
// B pairs loaded directly as packed 64-bit from smem (no MOV repacking).
__device__ __forceinline__ void mma_tile(const float (&As)[16][128],
                                         const float (&Bs)[16][128],
                                         int tm, int tn, ull (&acc)[8][4]) {
#pragma unroll
    for (int kk = 0; kk < 16; kk++) {
        float4 a0 = *(const float4*)&As[kk][tm * 4];
        float4 a1 = *(const float4*)&As[kk][64 + tm * 4];
        ulonglong2 b0 = *(const ulonglong2*)&Bs[kk][tn * 4];
        ulonglong2 b1 = *(const ulonglong2*)&Bs[kk][64 + tn * 4];
        float av[8] = {a0.x, a0.y, a0.z, a0.w, a1.x, a1.y, a1.z, a1.w};
#pragma unroll
        for (int i = 0; i < 8; i++) {
            ull ad = pack2(av[i]);
            ffma2(acc[i][0], ad, b0.x);
            ffma2(acc[i][1], ad, b0.y);
            ffma2(acc[i][2], ad, b1.x);
            ffma2(acc[i][3], ad, b1.y);
        }
    }
}

// Shared recurrent 128x128 GEMM tile: C_partial = A[:, k0:k0+16*ktiles] @ W-slice^T
__device__ __forceinline__ void rec_tile(
    const float* __restrict__ ap0, const float* __restrict__ ap1,
    const float* __restrict__ wp0, const float* __restrict__ wp1,
    int k0, int ktiles, float* __restrict__ outp, int Ntot, int n0,
    float (&As)[16][128], float (&Bs)[16][128])
{
    int tid = threadIdx.x;
    int tm = tid & 15, tn = tid >> 4;
    int ar0 = tid >> 2, ar1 = ar0 + 64;
    int akq = (tid & 3) * 4;

    ull acc[8][4];
#pragma unroll
    for (int i = 0; i < 8; i++)
#pragma unroll
        for (int j = 0; j < 4; j++) acc[i][j] = 0ull;

    float4 av0 = *(const float4*)(ap0 + k0 + akq);
    float4 av1 = *(const float4*)(ap1 + k0 + akq);
    float4 bv0 = *(const float4*)(wp0 + k0 + akq);
    float4 bv1 = *(const float4*)(wp1 + k0 + akq);

    for (int kt = 0; kt < ktiles; ++kt) {
        As[akq + 0][ar0] = av0.x; As[akq + 1][ar0] = av0.y;
        As[akq + 2][ar0] = av0.z; As[akq + 3][ar0] = av0.w;
        As[akq + 0][ar1] = av1.x; As[akq + 1][ar1] = av1.y;
        As[akq + 2][ar1] = av1.z; As[akq + 3][ar1] = av1.w;
        Bs[akq + 0][ar0] = bv0.x; Bs[akq + 1][ar0] = bv0.y;
        Bs[akq + 2][ar0] = bv0.z; Bs[akq + 3][ar0] = bv0.w;
        Bs[akq + 0][ar1] = bv1.x; Bs[akq + 1][ar1] = bv1.y;
        Bs[akq + 2][ar1] = bv1.z; Bs[akq + 3][ar1] = bv1.w;
        __syncthreads();
        if (kt + 1 < ktiles) {
            k0 += 16;
            av0 = *(const float4*)(ap0 + k0 + akq);
            av1 = *(const float4*)(ap1 + k0 + akq);
            bv0 = *(const float4*)(wp0 + k0 + akq);
            bv1 = *(const float4*)(wp1 + k0 + akq);
        }
        mma_tile(As, Bs, tm, tn, acc);
        __syncthreads();
    }

#pragma unroll
    for (int i = 0; i < 8; i++) {
        int m = (i < 4) ? tm * 4 + i : 64 + tm * 4 + (i - 4);
        float* dst = outp + (size_t)m * Ntot + n0;
        float2 p0 = unpack2(acc[i][0]), p1 = unpack2(acc[i][1]);
        float2 p2 = unpack2(acc[i][2]), p3 = unpack2(acc[i][3]);
        *(float4*)(dst + tn * 4)      = make_float4(p0.x, p0.y, p1.x, p1.y);
        *(float4*)(dst + 64 + tn * 4) = make_float4(p2.x, p2.y, p3.x, p3.y);
    }
}

// ---------- kernel 1: x-projection for all (t, b) at once ----------
__global__ void __launch_bounds__(256) xproj_kernel(
    const float* __restrict__ x,
    const float* __restrict__ Wz, const float* __restrict__ bz,
    const float* __restrict__ Wr, const float* __restrict__ br,
    const float* __restrict__ Wi, const float* __restrict__ bi)
{
    __shared__ float As[16][128];
    __shared__ float Bs[16][128];
    int tid = threadIdx.x;
    int g = blockIdx.x >> 3;                 // gate: 0=z 1=r 2=i
    int nloc0 = (blockIdx.x & 7) * 128;      // column within gate
    int m0 = blockIdx.y * 128;
    const float* W    = (g == 0) ? Wz : ((g == 1) ? Wr : Wi);
    const float* bias = (g == 0) ? bz : ((g == 1) ? br : bi);
    float* Xg         = (g == 0) ? g_xz : ((g == 1) ? g_xr : g_xi);

    int tm = tid & 15, tn = tid >> 4;
    int ar0 = tid >> 2, ar1 = ar0 + 64;
    int akq = (tid & 3) * 4;
    const float* ap0 = x + (size_t)(m0 + ar0) * DD;
    const float* ap1 = x + (size_t)(m0 + ar1) * DD;
    const float* wp0 = W + (size_t)(nloc0 + ar0) * 1536;
    const float* wp1 = W + (size_t)(nloc0 + ar1) * 1536;

    ull acc[8][4];
#pragma unroll
    for (int i = 0; i < 8; i++)
#pragma unroll
        for (int j = 0; j < 4; j++) acc[i][j] = 0ull;

    int k0 = 0;
    float4 av0 = *(const float4*)(ap0 + k0 + akq);
    float4 av1 = *(const float4*)(ap1 + k0 + akq);
    float4 bv0 = *(const float4*)(wp0 + k0 + akq);
    float4 bv1 = *(const float4*)(wp1 + k0 + akq);

    const int KT = DD / 16;  // 32
    for (int kt = 0; kt < KT; ++kt) {
        As[akq + 0][ar0] = av0.x; As[akq + 1][ar0] = av0.y;
        As[akq + 2][ar0] = av0.z; As[akq + 3][ar0] = av0.w;
        As[akq + 0][ar1] = av1.x; As[akq + 1][ar1] = av1.y;
        As[akq + 2][ar1] = av1.z; As[akq + 3][ar1] = av1.w;
        Bs[akq + 0][ar0] = bv0.x; Bs[akq + 1][ar0] = bv0.y;
        Bs[akq + 2][ar0] = bv0.z; Bs[akq + 3][ar0] = bv0.w;
        Bs[akq + 0][ar1] = bv1.x; Bs[akq + 1][ar1] = bv1.y;
        Bs[akq + 2][ar1] = bv1.z; Bs[akq + 3][ar1] = bv1.w;
        __syncthreads();
        if (kt + 1 < KT) {
            k0 += 16;
            av0 = *(const float4*)(ap0 + k0 + akq);
            av1 = *(const float4*)(ap1 + k0 + akq);
            bv0 = *(const float4*)(wp0 + k0 + akq);
            bv1 = *(const float4*)(wp1 + k0 + akq);
        }
        mma_tile(As, Bs, tm, tn, acc);
        __syncthreads();
    }

    float4 bias0 = *(const float4*)(bias + nloc0 + tn * 4);
    float4 bias1 = *(const float4*)(bias + nloc0 + 64 + tn * 4);
#pragma unroll
    for (int i = 0; i < 8; i++) {
        int m = m0 + ((i < 4) ? tm * 4 + i : 64 + tm * 4 + (i - 4));
        int bidx = m >> 8;      // / T  (row m = b*T + t)
        int t    = m & 255;     // % T
        float* dst = Xg + (size_t)t * (BB * LL) + (size_t)bidx * LL + nloc0;
        float2 p0 = unpack2(acc[i][0]), p1 = unpack2(acc[i][1]);
        float2 p2 = unpack2(acc[i][2]), p3 = unpack2(acc[i][3]);
        *(float4*)(dst + tn * 4) =
            make_float4(p0.x + bias0.x, p0.y + bias0.y, p1.x + bias0.z, p1.y + bias0.w);
        *(float4*)(dst + 64 + tn * 4) =
            make_float4(p2.x + bias1.x, p2.y + bias1.y, p3.x + bias1.z, p3.y + bias1.w);
    }
}

// ---------- kernel 2: the whole recurrence, persistent, one launch ----------
__global__ void __launch_bounds__(256, 1) gru_persistent(
    const float* __restrict__ Wz, const float* __restrict__ Wr,
    const float* __restrict__ Wi, float* __restrict__ out)
{
    __shared__ float As[16][128];
    __shared__ float Bs[16][128];
    int tid = threadIdx.x;
    int bx = blockIdx.x;
    unsigned target = 0;

    // init h = 0 (BB*LL/4 = 32768 float4 across 128*256 threads)
    {
        int e = bx * 256 + tid;
        ((float4*)g_h)[e] = make_float4(0.f, 0.f, 0.f, 0.f);
    }
    target += NB; grid_sync(target);

    for (int t = 0; t < TT; ++t) {
        // ---- Phase A: z|r gate GEMM partials: h @ [Wzh | Wrh]^T ----
        {
            int kidx = bx >> 4;            // 0..7, K-slice of 128
            int n0 = (bx & 15) * 128;      // 0..1920 over N=2048
            int ar0 = tid >> 2, ar1 = ar0 + 64;
            const float* ap0 = g_h + (size_t)ar0 * LL;
            const float* ap1 = g_h + (size_t)ar1 * LL;
            int na0 = n0 + ar0, na1 = n0 + ar1;
            const float* wp0 = ((na0 < 1024) ? Wz + (size_t)na0 * 1536
                                             : Wr + (size_t)(na0 - 1024) * 1536) + 512;
            const float* wp1 = ((na1 < 1024) ? Wz + (size_t)na1 * 1536
                                             : Wr + (size_t)(na1 - 1024) * 1536) + 512;
            rec_tile(ap0, ap1, wp0, wp1, kidx * 128, 8,
                     g_p1 + (size_t)kidx * BB * 2048, 2048, n0, As, Bs);
        }
        target += NB; grid_sync(target);

        // ---- Phase B: reduce1 -> z, rh ----
        {
            int e = bx * 256 + tid;          // float4 index over [B][L]
            int b = e >> 8, l4 = e & 255;
            const float4* P = (const float4*)g_p1;
            float4 zs = ((const float4*)g_xz)[(size_t)t * (BB * LL / 4) + e];
            float4 rs = ((const float4*)g_xr)[(size_t)t * (BB * LL / 4) + e];
#pragma unroll
            for (int k = 0; k < 8; k++) {
                float4 pz = P[(size_t)k * 65536 + b * 512 + l4];
                float4 pr = P[(size_t)k * 65536 + b * 512 + 256 + l4];
                zs.x += pz.x; zs.y += pz.y; zs.z += pz.z; zs.w += pz.w;
                rs.x += pr.x; rs.y += pr.y; rs.z += pr.z; rs.w += pr.w;
            }
            float4 z, r;
            z.x = 1.f / (1.f + __expf(-zs.x)); z.y = 1.f / (1.f + __expf(-zs.y));
            z.z = 1.f / (1.f + __expf(-zs.z)); z.w = 1.f / (1.f + __expf(-zs.w));
            r.x = 1.f / (1.f + __expf(-rs.x)); r.y = 1.f / (1.f + __expf(-rs.y));
            r.z = 1.f / (1.f + __expf(-rs.z)); r.w = 1.f / (1.f + __expf(-rs.w));
            float4 h = ((const float4*)g_h)[e];
            ((float4*)g_z)[e] = z;
            ((float4*)g_rh)[e] = make_float4(r.x * h.x, r.y * h.y, r.z * h.z, r.w * h.w);
        }
        target += NB; grid_sync(target);

        // ---- Phase C: candidate GEMM partials: (r*h) @ Wih^T ----
        {
            int kidx = bx >> 3;            // 0..15, K-slice of 64
            int n0 = (bx & 7) * 128;       // 0..896 over N=1024
            int ar0 = tid >> 2, ar1 = ar0 + 64;
            const float* ap0 = g_rh + (size_t)ar0 * LL;
            const float* ap1 = g_rh + (size_t)ar1 * LL;
            const float* wp0 = Wi + (size_t)(n0 + ar0) * 1536 + 512;
            const float* wp1 = Wi + (size_t)(n0 + ar1) * 1536 + 512;
            rec_tile(ap0, ap1, wp0, wp1, kidx * 64, 4,
                     g_p2 + (size_t)kidx * BB * LL, 1024, n0, As, Bs);
        }
        target += NB; grid_sync(target);

        // ---- Phase D: reduce2 -> h_new, emit history ----
        {
            int e = bx * 256 + tid;
            float4 c = ((const float4*)g_xi)[(size_t)t * (BB * LL / 4) + e];
            const float4* P = (const float4*)g_p2;
#pragma unroll
            for (int k = 0; k < 16; k++) {
                float4 p = P[(size_t)k * 32768 + e];
                c.x += p.x; c.y += p.y; c.z += p.z; c.w += p.w;
            }
            float4 z = ((const float4*)g_z)[e];
            float4 h = ((const float4*)g_h)[e];
            float4 hn;
            hn.x = (1.f - z.x) * h.x + z.x * tanhf(c.x);
            hn.y = (1.f - z.y) * h.y + z.y * tanhf(c.y);
            hn.z = (1.f - z.z) * h.z + z.z * tanhf(c.z);
            hn.w = (1.f - z.w) * h.w + z.w * tanhf(c.w);
            ((float4*)g_h)[e] = hn;
            ((float4*)out)[(size_t)t * (BB * LL / 4) + e] = hn;
        }
        target += NB; grid_sync(target);
    }

    // ---- exit protocol: last CTA out resets the barrier counters ----
    if (tid == 0) {
        __threadfence();
        unsigned done = atomicAdd(&g_bar2, 1u) + 1;
        if (done == NB) {
            g_bar1 = 0;
            g_bar2 = 0;
            __threadfence();
        }
    }
}

extern "C" void kernel_launch(void* const* d_in, const int* in_sizes, int n_in,
                              void* d_out, int out_size) {
    const float* x  = (const float*)d_in[0];
    const float* Wz = (const float*)d_in[1];
    const float* bz = (const float*)d_in[2];
    const float* Wr = (const float*)d_in[3];
    const float* br = (const float*)d_in[4];
    const float* Wi = (const float*)d_in[5];
    const float* bi = (const float*)d_in[6];
    float* out = (float*)d_out;

    xproj_kernel<<<dim3(24, 256), 256>>>(x, Wz, bz, Wr, br, Wi, bi);
    gru_persistent<<<NB, 256>>>(Wz, Wr, Wi, out);
}

// round 3
// speedup vs baseline: 1.0593x; 1.0593x over previous
#include <cuda_runtime.h>
#include <math.h>

#define BB 128
#define TT 256
#define DD 512
#define LL 1024
#define NB 128   // persistent grid size (<=148 SMs -> co-resident)

// ---------- scratch (static device memory; no allocations) ----------
__device__ __align__(16) float g_xz[TT * BB * LL];   // x @ Wz_x^T + bz, [t][b][l]
__device__ __align__(16) float g_xr[TT * BB * LL];
__device__ __align__(16) float g_xi[TT * BB * LL];
__device__ __align__(16) float g_h [BB * LL];        // current hidden
__device__ __align__(16) float g_z [BB * LL];        // update gate for current step
__device__ __align__(16) float g_rh[BB * LL];        // r * h for current step
__device__ __align__(16) float g_p1[8  * BB * 2048]; // K-split partials, phase 1
__device__ __align__(16) float g_p2[16 * BB * LL];   // K-split partials, phase 2
__device__ unsigned g_bar1 = 0;                      // grid barrier arrive counter
__device__ unsigned g_bar2 = 0;                      // exit confirmation counter

typedef unsigned long long ull;

__device__ __forceinline__ ull pack2(float v) {
    ull r; asm("mov.b64 %0, {%1, %1};" : "=l"(r) : "f"(v)); return r;
}
__device__ __forceinline__ void ffma2(ull& d, ull a, ull b) {
    asm("fma.rn.f32x2 %0, %1, %2, %0;" : "+l"(d) : "l"(a), "l"(b));
}
__device__ __forceinline__ float2 unpack2(ull v) {
    float2 f; asm("mov.b64 {%0, %1}, %2;" : "=f"(f.x), "=f"(f.y) : "l"(v)); return f;
}

// Software grid barrier: 128 CTAs, cumulative counter. Thread 0 arrives + spins.
__device__ __forceinline__ void grid_sync(unsigned target) {
    __syncthreads();
    if (threadIdx.x == 0) {
        __threadfence();
        atomicAdd(&g_bar1, 1u);
        unsigned v;
        do {
            asm volatile("ld.acquire.gpu.u32 %0, [%1];" : "=r"(v) : "l"(&g_bar1));
        } while (v < target);
    }
    __syncthreads();
}

// ================= xproj (unchanged, known-good) =================
__device__ __forceinline__ void mma_tile16(const float (&As)[16][128],
                                           const float (&Bs)[16][128],
                                           int tm, int tn, ull (&acc)[8][4]) {
#pragma unroll
    for (int kk = 0; kk < 16; kk++) {
        float4 a0 = *(const float4*)&As[kk][tm * 4];
        float4 a1 = *(const float4*)&As[kk][64 + tm * 4];
        ulonglong2 b0 = *(const ulonglong2*)&Bs[kk][tn * 4];
        ulonglong2 b1 = *(const ulonglong2*)&Bs[kk][64 + tn * 4];
        float av[8] = {a0.x, a0.y, a0.z, a0.w, a1.x, a1.y, a1.z, a1.w};
#pragma unroll
        for (int i = 0; i < 8; i++) {
            ull ad = pack2(av[i]);
            ffma2(acc[i][0], ad, b0.x);
            ffma2(acc[i][1], ad, b0.y);
            ffma2(acc[i][2], ad, b1.x);
            ffma2(acc[i][3], ad, b1.y);
        }
    }
}

__global__ void __launch_bounds__(256) xproj_kernel(
    const float* __restrict__ x,
    const float* __restrict__ Wz, const float* __restrict__ bz,
    const float* __restrict__ Wr, const float* __restrict__ br,
    const float* __restrict__ Wi, const float* __restrict__ bi)
{
    __shared__ float As[16][128];
    __shared__ float Bs[16][128];
    int tid = threadIdx.x;
    int g = blockIdx.x >> 3;
    int nloc0 = (blockIdx.x & 7) * 128;
    int m0 = blockIdx.y * 128;
    const float* W    = (g == 0) ? Wz : ((g == 1) ? Wr : Wi);
    const float* bias = (g == 0) ? bz : ((g == 1) ? br : bi);
    float* Xg         = (g == 0) ? g_xz : ((g == 1) ? g_xr : g_xi);

    int tm = tid & 15, tn = tid >> 4;
    int ar0 = tid >> 2, ar1 = ar0 + 64;
    int akq = (tid & 3) * 4;
    const float* ap0 = x + (size_t)(m0 + ar0) * DD;
    const float* ap1 = x + (size_t)(m0 + ar1) * DD;
    const float* wp0 = W + (size_t)(nloc0 + ar0) * 1536;
    const float* wp1 = W + (size_t)(nloc0 + ar1) * 1536;

    ull acc[8][4];
#pragma unroll
    for (int i = 0; i < 8; i++)
#pragma unroll
        for (int j = 0; j < 4; j++) acc[i][j] = 0ull;

    int k0 = 0;
    float4 av0 = *(const float4*)(ap0 + k0 + akq);
    float4 av1 = *(const float4*)(ap1 + k0 + akq);
    float4 bv0 = *(const float4*)(wp0 + k0 + akq);
    float4 bv1 = *(const float4*)(wp1 + k0 + akq);

    const int KT = DD / 16;  // 32
    for (int kt = 0; kt < KT; ++kt) {
        As[akq + 0][ar0] = av0.x; As[akq + 1][ar0] = av0.y;
        As[akq + 2][ar0] = av0.z; As[akq + 3][ar0] = av0.w;
        As[akq + 0][ar1] = av1.x; As[akq + 1][ar1] = av1.y;
        As[akq + 2][ar1] = av1.z; As[akq + 3][ar1] = av1.w;
        Bs[akq + 0][ar0] = bv0.x; Bs[akq + 1][ar0] = bv0.y;
        Bs[akq + 2][ar0] = bv0.z; Bs[akq + 3][ar0] = bv0.w;
        Bs[akq + 0][ar1] = bv1.x; Bs[akq + 1][ar1] = bv1.y;
        Bs[akq + 2][ar1] = bv1.z; Bs[akq + 3][ar1] = bv1.w;
        __syncthreads();
        if (kt + 1 < KT) {
            k0 += 16;
            av0 = *(const float4*)(ap0 + k0 + akq);
            av1 = *(const float4*)(ap1 + k0 + akq);
            bv0 = *(const float4*)(wp0 + k0 + akq);
            bv1 = *(const float4*)(wp1 + k0 + akq);
        }
        mma_tile16(As, Bs, tm, tn, acc);
        __syncthreads();
    }

    float4 bias0 = *(const float4*)(bias + nloc0 + tn * 4);
    float4 bias1 = *(const float4*)(bias + nloc0 + 64 + tn * 4);
#pragma unroll
    for (int i = 0; i < 8; i++) {
        int m = m0 + ((i < 4) ? tm * 4 + i : 64 + tm * 4 + (i - 4));
        int bidx = m >> 8;      // row m = b*T + t
        int t    = m & 255;
        float* dst = Xg + (size_t)t * (BB * LL) + (size_t)bidx * LL + nloc0;
        float2 p0 = unpack2(acc[i][0]), p1 = unpack2(acc[i][1]);
        float2 p2 = unpack2(acc[i][2]), p3 = unpack2(acc[i][3]);
        *(float4*)(dst + tn * 4) =
            make_float4(p0.x + bias0.x, p0.y + bias0.y, p1.x + bias0.z, p1.y + bias0.w);
        *(float4*)(dst + 64 + tn * 4) =
            make_float4(p2.x + bias1.x, p2.y + bias1.y, p3.x + bias1.z, p3.y + bias1.w);
    }
}

// ================= persistent recurrence =================
// Dynamic smem layout (floats):
//   Wa  [128][128]  transposed phase-A weight slice   (64 KB)
//   Wc  [ 64][128]  transposed phase-C weight slice   (32 KB)
//   At  [128][128]  staged transposed A operand       (64 KB)
#define SM_WA 0
#define SM_WC 16384
#define SM_AT 24576
#define SMEM_FLOATS 40960

// Transposed stage: dst[k][row] (row-contig) from src rows (stride srcStride),
// slice cols [c0, c0+width). 4x4 register transpose, STS.128.
__device__ __forceinline__ void stage_T(float* __restrict__ dst,
                                        const float* __restrict__ src,
                                        int srcStride, int c0, int width) {
    int tid = threadIdx.x;
    int b = (tid & 31) * 4;
    int iters = width >> 5;               // width/4 k-quads / 8 kq-groups
    for (int i = 0; i < iters; i++) {
        int kq = (tid >> 5) + 8 * i;      // k-quad index
        const float* s = src + c0 + kq * 4;
        float4 r0 = *(const float4*)(s + (size_t)(b + 0) * srcStride);
        float4 r1 = *(const float4*)(s + (size_t)(b + 1) * srcStride);
        float4 r2 = *(const float4*)(s + (size_t)(b + 2) * srcStride);
        float4 r3 = *(const float4*)(s + (size_t)(b + 3) * srcStride);
        int kl = kq * 4;
        *(float4*)&dst[(kl + 0) * 128 + b] = make_float4(r0.x, r1.x, r2.x, r3.x);
        *(float4*)&dst[(kl + 1) * 128 + b] = make_float4(r0.y, r1.y, r2.y, r3.y);
        *(float4*)&dst[(kl + 2) * 128 + b] = make_float4(r0.z, r1.z, r2.z, r3.z);
        *(float4*)&dst[(kl + 3) * 128 + b] = make_float4(r0.w, r1.w, r2.w, r3.w);
    }
}

// Sync-free 128x128 GEMM from smem-resident transposed operands.
__device__ __forceinline__ void gemm_sm(const float* __restrict__ At,
                                        const float* __restrict__ Wt,
                                        int K, int tm, int tn, ull (&acc)[8][4]) {
#pragma unroll
    for (int i = 0; i < 8; i++)
#pragma unroll
        for (int j = 0; j < 4; j++) acc[i][j] = 0ull;
#pragma unroll 8
    for (int kk = 0; kk < K; kk++) {
        float4 a0 = *(const float4*)&At[kk * 128 + tm * 4];
        float4 a1 = *(const float4*)&At[kk * 128 + 64 + tm * 4];
        ulonglong2 b0 = *(const ulonglong2*)&Wt[kk * 128 + tn * 4];
        ulonglong2 b1 = *(const ulonglong2*)&Wt[kk * 128 + 64 + tn * 4];
        float av[8] = {a0.x, a0.y, a0.z, a0.w, a1.x, a1.y, a1.z, a1.w};
#pragma unroll
        for (int i = 0; i < 8; i++) {
            ull ad = pack2(av[i]);
            ffma2(acc[i][0], ad, b0.x);
            ffma2(acc[i][1], ad, b0.y);
            ffma2(acc[i][2], ad, b1.x);
            ffma2(acc[i][3], ad, b1.y);
        }
    }
}

__device__ __forceinline__ void store_partials(float* __restrict__ outp, int Ntot,
                                               int n0, int tm, int tn,
                                               const ull (&acc)[8][4]) {
#pragma unroll
    for (int i = 0; i < 8; i++) {
        int m = (i < 4) ? tm * 4 + i : 64 + tm * 4 + (i - 4);
        float* dst = outp + (size_t)m * Ntot + n0;
        float2 p0 = unpack2(acc[i][0]), p1 = unpack2(acc[i][1]);
        float2 p2 = unpack2(acc[i][2]), p3 = unpack2(acc[i][3]);
        *(float4*)(dst + tn * 4)      = make_float4(p0.x, p0.y, p1.x, p1.y);
        *(float4*)(dst + 64 + tn * 4) = make_float4(p2.x, p2.y, p3.x, p3.y);
    }
}

__global__ void __launch_bounds__(256, 1) gru_persistent(
    const float* __restrict__ Wz, const float* __restrict__ Wr,
    const float* __restrict__ Wi, float* __restrict__ out)
{
    extern __shared__ float sm[];
    float* Wa = sm + SM_WA;
    float* Wc = sm + SM_WC;
    float* At = sm + SM_AT;

    int tid = threadIdx.x;
    int bx = blockIdx.x;
    int tm = tid & 15, tn = tid >> 4;
    unsigned target = 0;

    // CTA's fixed roles
    int kidxA = bx >> 4;            // 0..7  (phase-A K-slice of 128)
    int n0A   = (bx & 15) * 128;    // 0..1920 over N=2048
    int kidxC = bx >> 3;            // 0..15 (phase-C K-slice of 64)
    int n0C   = (bx & 7) * 128;     // 0..896 over N=1024

    // ---- one-time: preload transposed weight slices (reused all 256 steps) ----
    {
        const float* wbaseA = ((n0A < 1024) ? Wz + (size_t)n0A * 1536
                                            : Wr + (size_t)(n0A - 1024) * 1536);
        stage_T(Wa, wbaseA, 1536, 512 + kidxA * 128, 128);
        const float* wbaseC = Wi + (size_t)n0C * 1536;
        stage_T(Wc, wbaseC, 1536, 512 + kidxC * 64, 64);
    }

    // init h = 0
    {
        int e = bx * 256 + tid;
        ((float4*)g_h)[e] = make_float4(0.f, 0.f, 0.f, 0.f);
    }
    target += NB; grid_sync(target);

    for (int t = 0; t < TT; ++t) {
        // ---- Phase A: z|r gate GEMM partials: h @ [Wzh | Wrh]^T ----
        {
            stage_T(At, g_h, LL, kidxA * 128, 128);
            __syncthreads();
            ull acc[8][4];
            gemm_sm(At, Wa, 128, tm, tn, acc);
            store_partials(g_p1 + (size_t)kidxA * BB * 2048, 2048, n0A, tm, tn, acc);
        }
        target += NB; grid_sync(target);

        // ---- Phase B: reduce1 -> z, rh ----
        {
            int e = bx * 256 + tid;          // float4 index over [B][L]
            int b = e >> 8, l4 = e & 255;
            const float4* P = (const float4*)g_p1;
            float4 zs = ((const float4*)g_xz)[(size_t)t * (BB * LL / 4) + e];
            float4 rs = ((const float4*)g_xr)[(size_t)t * (BB * LL / 4) + e];
#pragma unroll
            for (int k = 0; k < 8; k++) {
                float4 pz = P[(size_t)k * 65536 + b * 512 + l4];
                float4 pr = P[(size_t)k * 65536 + b * 512 + 256 + l4];
                zs.x += pz.x; zs.y += pz.y; zs.z += pz.z; zs.w += pz.w;
                rs.x += pr.x; rs.y += pr.y; rs.z += pr.z; rs.w += pr.w;
            }
            float4 z, r;
            z.x = 1.f / (1.f + __expf(-zs.x)); z.y = 1.f / (1.f + __expf(-zs.y));
            z.z = 1.f / (1.f + __expf(-zs.z)); z.w = 1.f / (1.f + __expf(-zs.w));
            r.x = 1.f / (1.f + __expf(-rs.x)); r.y = 1.f / (1.f + __expf(-rs.y));
            r.z = 1.f / (1.f + __expf(-rs.z)); r.w = 1.f / (1.f + __expf(-rs.w));
            float4 h = ((const float4*)g_h)[e];
            ((float4*)g_z)[e] = z;
            ((float4*)g_rh)[e] = make_float4(r.x * h.x, r.y * h.y, r.z * h.z, r.w * h.w);
        }
        target += NB; grid_sync(target);

        // ---- Phase C: candidate GEMM partials: (r*h) @ Wih^T ----
        {
            __syncthreads();   // ensure prior At readers done (cheap; all arrived barrier)
            stage_T(At, g_rh, LL, kidxC * 64, 64);
            __syncthreads();
            ull acc[8][4];
            gemm_sm(At, Wc, 64, tm, tn, acc);
            store_partials(g_p2 + (size_t)kidxC * BB * LL, 1024, n0C, tm, tn, acc);
        }
        target += NB; grid_sync(target);

        // ---- Phase D: reduce2 -> h_new, emit history ----
        {
            int e = bx * 256 + tid;
            float4 c = ((const float4*)g_xi)[(size_t)t * (BB * LL / 4) + e];
            const float4* P = (const float4*)g_p2;
#pragma unroll
            for (int k = 0; k < 16; k++) {
                float4 p = P[(size_t)k * 32768 + e];
                c.x += p.x; c.y += p.y; c.z += p.z; c.w += p.w;
            }
            float4 z = ((const float4*)g_z)[e];
            float4 h = ((const float4*)g_h)[e];
            float4 hn;
            hn.x = (1.f - z.x) * h.x + z.x * tanhf(c.x);
            hn.y = (1.f - z.y) * h.y + z.y * tanhf(c.y);
            hn.z = (1.f - z.z) * h.z + z.z * tanhf(c.z);
            hn.w = (1.f - z.w) * h.w + z.w * tanhf(c.w);
            ((float4*)g_h)[e] = hn;
            ((float4*)out)[(size_t)t * (BB * LL / 4) + e] = hn;
        }
        target += NB; grid_sync(target);
    }

    // ---- exit protocol: last CTA out resets the barrier counters ----
    if (tid == 0) {
        __threadfence();
        unsigned done = atomicAdd(&g_bar2, 1u) + 1;
        if (done == NB) {
            g_bar1 = 0;
            g_bar2 = 0;
            __threadfence();
        }
    }
}

extern "C" void kernel_launch(void* const* d_in, const int* in_sizes, int n_in,
                              void* d_out, int out_size) {
    const float* x  = (const float*)d_in[0];
    const float* Wz = (const float*)d_in[1];
    const float* bz = (const float*)d_in[2];
    const float* Wr = (const float*)d_in[3];
    const float* br = (const float*)d_in[4];
    const float* Wi = (const float*)d_in[5];
    const float* bi = (const float*)d_in[6];
    float* out = (float*)d_out;

    cudaFuncSetAttribute(gru_persistent,
                         cudaFuncAttributeMaxDynamicSharedMemorySize,
                         SMEM_FLOATS * sizeof(float));

    xproj_kernel<<<dim3(24, 256), 256>>>(x, Wz, bz, Wr, br, Wi, bi);
    gru_persistent<<<NB, 256, SMEM_FLOATS * sizeof(float)>>>(Wz, Wr, Wi, out);
}

// round 5
// speedup vs baseline: 1.6358x; 1.5443x over previous
#include <cuda_runtime.h>
#include <cuda_bf16.h>
#include <math.h>

#define BB 128
#define TT 256
#define DD 512
#define LL 1024
#define NB 128   // persistent grid size (<=148 SMs -> co-resident)

// ---------- scratch (static device memory; no allocations) ----------
__device__ __align__(16) float g_xz[TT * BB * LL];   // x @ Wz_x^T + bz, [t][b][l]
__device__ __align__(16) float g_xr[TT * BB * LL];
__device__ __align__(16) float g_xi[TT * BB * LL];
__device__ __align__(16) float g_h [BB * LL];        // current hidden
__device__ __align__(16) float g_z [BB * LL];        // update gate for current step
__device__ __align__(16) float g_rh[BB * LL];        // r * h for current step
__device__ __align__(16) float g_p1[8  * BB * 2048]; // K-split partials, phase 1
__device__ __align__(16) float g_p2[16 * BB * LL];   // K-split partials, phase 2
__device__ unsigned g_bar1 = 0;
__device__ unsigned g_bar2 = 0;

// ---- software grid barrier (persistent kernel; classic syncthreads+fence+atomic) ----
__device__ __forceinline__ void grid_sync(unsigned target) {
    __syncthreads();
    if (threadIdx.x == 0) {
        __threadfence();
        atomicAdd(&g_bar1, 1u);
        unsigned v;
        do {
            asm volatile("ld.acquire.gpu.u32 %0, [%1];" : "=r"(v) : "l"(&g_bar1));
        } while (v < target);
    }
    __syncthreads();
}

// ---- portable tensor-core primitives (compute_80-class; no sm_103a-only features) ----
__device__ __forceinline__ unsigned smem_u32(const void* p) {
    unsigned a;
    asm("{ .reg .u64 t; cvta.to.shared.u64 t, %1; cvt.u32.u64 %0, t; }" : "=r"(a) : "l"(p));
    return a;
}
__device__ __forceinline__ void ldsm4(unsigned (&r)[4], unsigned addr) {
    asm volatile("ldmatrix.sync.aligned.m8n8.x4.shared.b16 {%0,%1,%2,%3}, [%4];"
                 : "=r"(r[0]), "=r"(r[1]), "=r"(r[2]), "=r"(r[3]) : "r"(addr));
}
__device__ __forceinline__ void mma16816(float (&d)[4], const unsigned (&a)[4],
                                         unsigned b0, unsigned b1) {
    asm volatile("mma.sync.aligned.m16n8k16.row.col.f32.bf16.bf16.f32 "
                 "{%0,%1,%2,%3}, {%4,%5,%6,%7}, {%8,%9}, {%0,%1,%2,%3};"
                 : "+f"(d[0]), "+f"(d[1]), "+f"(d[2]), "+f"(d[3])
                 : "r"(a[0]), "r"(a[1]), "r"(a[2]), "r"(a[3]), "r"(b0), "r"(b1));
}

// ---- fp32 -> (bf16 hi, bf16 lo) split-stage into padded-row smem tile ----
// dst[row][k] row-major with row stride SST bf16 elements. 256 threads, 128 rows.
template<int WIDTH, int SST>
__device__ __forceinline__ void stage_pad(char* __restrict__ hiB, char* __restrict__ loB,
                                          const float* __restrict__ src, int srcStride, int c0)
{
    int tid = threadIdx.x;
    int r = tid >> 1, half = tid & 1;
    const int CH = WIDTH / 2;
    int kl0 = half * CH;
    const float* s = src + (size_t)r * srcStride + c0 + kl0;
    unsigned short* hp = (unsigned short*)hiB + r * SST + kl0;
    unsigned short* lp = (unsigned short*)loB + r * SST + kl0;
#pragma unroll
    for (int g = 0; g < CH / 8; g++) {
        float4 f0 = *(const float4*)(s + g * 8);
        float4 f1 = *(const float4*)(s + g * 8 + 4);
        float xs[8] = {f0.x, f0.y, f0.z, f0.w, f1.x, f1.y, f1.z, f1.w};
        unsigned hu[4], lu[4];
#pragma unroll
        for (int p = 0; p < 4; p++) {
            __nv_bfloat16 h0 = __float2bfloat16(xs[2 * p]);
            __nv_bfloat16 h1 = __float2bfloat16(xs[2 * p + 1]);
            float l0 = xs[2 * p]     - __bfloat162float(h0);
            float l1 = xs[2 * p + 1] - __bfloat162float(h1);
            __nv_bfloat16 lb0 = __float2bfloat16(l0);
            __nv_bfloat16 lb1 = __float2bfloat16(l1);
            hu[p] = (unsigned)__bfloat16_as_ushort(h0) | ((unsigned)__bfloat16_as_ushort(h1) << 16);
            lu[p] = (unsigned)__bfloat16_as_ushort(lb0) | ((unsigned)__bfloat16_as_ushort(lb1) << 16);
        }
        *(uint4*)(hp + g * 8) = make_uint4(hu[0], hu[1], hu[2], hu[3]);
        *(uint4*)(lp + g * 8) = make_uint4(lu[0], lu[1], lu[2], lu[3]);
    }
}

// ---- warp-tile GEMM: CTA 128x128, 8 warps as 2(m)x4(n), warp tile 64x32 ----
// acc[im][in8][4] over 4 m16 frags x 4 n8 frags. 3-term split-bf16 per k16.
template<int SSTA, int SSTB>
__device__ __forceinline__ void wgemm(unsigned aHi, unsigned aLo,
                                      unsigned bHi, unsigned bLo,
                                      int ksteps, float (&acc)[4][4][4])
{
    int lane = threadIdx.x & 31, wid = threadIdx.x >> 5;
    int m0w = (wid & 1) * 64, n0w = (wid >> 1) * 32;
    unsigned aoff = ((m0w + (lane & 15)) * SSTA + ((lane >> 4) << 3)) * 2;
    unsigned boff = ((n0w + (lane & 7) + ((lane >> 4) & 1) * 8) * SSTB
                     + (((lane >> 3) & 1) << 3)) * 2;
    for (int ks = 0; ks < ksteps; ks++) {
        unsigned ka = aoff + ks * 32, kb = boff + ks * 32;
        unsigned bh[2][4], bl[2][4];
        ldsm4(bh[0], bHi + kb);
        ldsm4(bh[1], bHi + kb + 16 * SSTB * 2);
        ldsm4(bl[0], bLo + kb);
        ldsm4(bl[1], bLo + kb + 16 * SSTB * 2);
#pragma unroll
        for (int im = 0; im < 4; im++) {
            unsigned ah[4], al[4];
            ldsm4(ah, aHi + ka + im * 16 * SSTA * 2);
            ldsm4(al, aLo + ka + im * 16 * SSTA * 2);
#pragma unroll
            for (int ib = 0; ib < 2; ib++) {
                mma16816(acc[im][ib * 2 + 0], ah, bh[ib][0], bh[ib][1]);
                mma16816(acc[im][ib * 2 + 1], ah, bh[ib][2], bh[ib][3]);
                mma16816(acc[im][ib * 2 + 0], ah, bl[ib][0], bl[ib][1]);
                mma16816(acc[im][ib * 2 + 1], ah, bl[ib][2], bl[ib][3]);
                mma16816(acc[im][ib * 2 + 0], al, bh[ib][0], bh[ib][1]);
                mma16816(acc[im][ib * 2 + 1], al, bh[ib][2], bh[ib][3]);
            }
        }
    }
}

__device__ __forceinline__ void zero_acc(float (&acc)[4][4][4]) {
#pragma unroll
    for (int i = 0; i < 4; i++)
#pragma unroll
        for (int j = 0; j < 4; j++)
#pragma unroll
            for (int q = 0; q < 4; q++) acc[i][j][q] = 0.f;
}

// acc -> global fp32 (row stride ldd)
__device__ __forceinline__ void store_acc(float* __restrict__ dst, int ldd,
                                          const float (&acc)[4][4][4])
{
    int lane = threadIdx.x & 31, wid = threadIdx.x >> 5;
    int m0w = (wid & 1) * 64, n0w = (wid >> 1) * 32;
    int r = lane >> 2, cp = (lane & 3) * 2;
#pragma unroll
    for (int im = 0; im < 4; im++)
#pragma unroll
        for (int in8 = 0; in8 < 4; in8++) {
            float* p = dst + (size_t)(m0w + im * 16 + r) * ldd + n0w + in8 * 8 + cp;
            *(float2*)p = make_float2(acc[im][in8][0], acc[im][in8][1]);
            *(float2*)(p + 8 * ldd) = make_float2(acc[im][in8][2], acc[im][in8][3]);
        }
}

// ================= xproj: x @ W_x^T + b, tensor cores =================
// grid (24, 256): 24 n-tiles (3 gates x 8), 256 m-tiles of 128 over B*T.
// smem: A hi/lo + W hi/lo, each 128 x 72(pad) bf16 = 18432 B.
#define XSST 72
#define XTB  18432
#define XP_SMEM (4 * XTB)

__global__ void __launch_bounds__(256) xproj_kernel(
    const float* __restrict__ x,
    const float* __restrict__ Wz, const float* __restrict__ bz,
    const float* __restrict__ Wr, const float* __restrict__ br,
    const float* __restrict__ Wi, const float* __restrict__ bi)
{
    extern __shared__ char smb[];
    __shared__ float sbias[128];
    char* AH = smb;
    char* AL = smb + XTB;
    char* WH = smb + 2 * XTB;
    char* WL = smb + 3 * XTB;

    int tid = threadIdx.x;
    int g = blockIdx.x >> 3;
    int n0 = (blockIdx.x & 7) * 128;
    int m0 = blockIdx.y * 128;
    const float* W    = (g == 0) ? Wz : ((g == 1) ? Wr : Wi);
    const float* bias = (g == 0) ? bz : ((g == 1) ? br : bi);
    float* Xg         = (g == 0) ? g_xz : ((g == 1) ? g_xr : g_xi);

    if (tid < 128) sbias[tid] = bias[n0 + tid];

    unsigned aHi = smem_u32(AH), aLo = smem_u32(AL);
    unsigned bHi = smem_u32(WH), bLo = smem_u32(WL);

    float acc[4][4][4];
    zero_acc(acc);

    for (int c = 0; c < 8; c++) {           // K=512 in 8 chunks of 64
        int k0 = c * 64;
        stage_pad<64, XSST>(AH, AL, x + (size_t)m0 * DD, DD, k0);
        stage_pad<64, XSST>(WH, WL, W + (size_t)n0 * 1536, 1536, k0);
        __syncthreads();
        wgemm<XSST, XSST>(aHi, aLo, bHi, bLo, 4, acc);
        __syncthreads();
    }

    // epilogue: bias + scatter to [t][b][l]
    int lane = tid & 31, wid = tid >> 5;
    int m0w = (wid & 1) * 64, n0w = (wid >> 1) * 32;
    int r = lane >> 2, cp = (lane & 3) * 2;
#pragma unroll
    for (int im = 0; im < 4; im++) {
#pragma unroll
        for (int in8 = 0; in8 < 4; in8++) {
            int col = n0w + in8 * 8 + cp;
            float b0 = sbias[col], b1 = sbias[col + 1];
            int m = m0 + m0w + im * 16 + r;
            int t = m & 255, b = m >> 8;
            float* p = Xg + (size_t)t * (BB * LL) + (size_t)b * LL + n0 + col;
            *(float2*)p = make_float2(acc[im][in8][0] + b0, acc[im][in8][1] + b1);
            int m2 = m + 8;
            int t2 = m2 & 255, b2 = m2 >> 8;
            float* p2 = Xg + (size_t)t2 * (BB * LL) + (size_t)b2 * LL + n0 + col;
            *(float2*)p2 = make_float2(acc[im][in8][2] + b0, acc[im][in8][3] + b1);
        }
    }
}

// ================= persistent recurrence (tensor cores) =================
// smem (bytes): AT hi/lo 128x136 (34816 each), WA hi/lo 128x136, WC hi/lo 128x72 (18432)
#define ASST 136
#define CSST 72
#define PR_AT_HI 0
#define PR_AT_LO 34816
#define PR_WA_HI 69632
#define PR_WA_LO 104448
#define PR_WC_HI 139264
#define PR_WC_LO 157696
#define PR_SMEM  176128

__global__ void __launch_bounds__(256) gru_persistent(
    const float* __restrict__ Wz, const float* __restrict__ Wr,
    const float* __restrict__ Wi, float* __restrict__ out)
{
    extern __shared__ char smb[];
    int tid = threadIdx.x;
    int bx = blockIdx.x;
    unsigned target = 0;

    unsigned atHi = smem_u32(smb + PR_AT_HI), atLo = smem_u32(smb + PR_AT_LO);
    unsigned waHi = smem_u32(smb + PR_WA_HI), waLo = smem_u32(smb + PR_WA_LO);
    unsigned wcHi = smem_u32(smb + PR_WC_HI), wcLo = smem_u32(smb + PR_WC_LO);

    // CTA roles
    int kidxA = bx >> 4;            // 0..7  (phase-A K-slice of 128)
    int n0A   = (bx & 15) * 128;    // over N=2048
    int kidxC = bx >> 3;            // 0..15 (phase-C K-slice of 64)
    int n0C   = (bx & 7) * 128;     // over N=1024

    // one-time: weight slices -> smem bf16 hi/lo (reused for all 256 steps)
    {
        const float* wbA = (n0A < 1024) ? Wz + (size_t)n0A * 1536
                                        : Wr + (size_t)(n0A - 1024) * 1536;
        stage_pad<128, ASST>(smb + PR_WA_HI, smb + PR_WA_LO, wbA, 1536, 512 + kidxA * 128);
        stage_pad<64, CSST>(smb + PR_WC_HI, smb + PR_WC_LO,
                            Wi + (size_t)n0C * 1536, 1536, 512 + kidxC * 64);
    }
    // init h = 0
    {
        int e = bx * 256 + tid;
        ((float4*)g_h)[e] = make_float4(0.f, 0.f, 0.f, 0.f);
    }
    target += NB; grid_sync(target);

    for (int t = 0; t < TT; ++t) {
        // ---- Phase A: h @ [Wzh | Wrh]^T partials (K-slice 128) ----
        {
            stage_pad<128, ASST>(smb + PR_AT_HI, smb + PR_AT_LO, g_h, LL, kidxA * 128);
            __syncthreads();
            float acc[4][4][4];
            zero_acc(acc);
            wgemm<ASST, ASST>(atHi, atLo, waHi, waLo, 8, acc);
            store_acc(g_p1 + (size_t)kidxA * BB * 2048 + n0A, 2048, acc);
        }
        target += NB; grid_sync(target);

        // ---- Phase B: reduce1 -> z, rh ----
        {
            int e = bx * 256 + tid;
            int b = e >> 8, l4 = e & 255;
            const float4* P = (const float4*)g_p1;
            float4 zs = ((const float4*)g_xz)[(size_t)t * (BB * LL / 4) + e];
            float4 rs = ((const float4*)g_xr)[(size_t)t * (BB * LL / 4) + e];
#pragma unroll
            for (int k = 0; k < 8; k++) {
                float4 pz = P[(size_t)k * 65536 + b * 512 + l4];
                float4 pr = P[(size_t)k * 65536 + b * 512 + 256 + l4];
                zs.x += pz.x; zs.y += pz.y; zs.z += pz.z; zs.w += pz.w;
                rs.x += pr.x; rs.y += pr.y; rs.z += pr.z; rs.w += pr.w;
            }
            float4 z, r;
            z.x = 1.f / (1.f + __expf(-zs.x)); z.y = 1.f / (1.f + __expf(-zs.y));
            z.z = 1.f / (1.f + __expf(-zs.z)); z.w = 1.f / (1.f + __expf(-zs.w));
            r.x = 1.f / (1.f + __expf(-rs.x)); r.y = 1.f / (1.f + __expf(-rs.y));
            r.z = 1.f / (1.f + __expf(-rs.z)); r.w = 1.f / (1.f + __expf(-rs.w));
            float4 h = ((const float4*)g_h)[e];
            ((float4*)g_z)[e] = z;
            ((float4*)g_rh)[e] = make_float4(r.x * h.x, r.y * h.y, r.z * h.z, r.w * h.w);
        }
        target += NB; grid_sync(target);

        // ---- Phase C: (r*h) @ Wih^T partials (K-slice 64) ----
        {
            stage_pad<64, ASST>(smb + PR_AT_HI, smb + PR_AT_LO, g_rh, LL, kidxC * 64);
            __syncthreads();
            float acc[4][4][4];
            zero_acc(acc);
            wgemm<ASST, CSST>(atHi, atLo, wcHi, wcLo, 4, acc);
            store_acc(g_p2 + (size_t)kidxC * BB * LL + n0C, 1024, acc);
        }
        target += NB; grid_sync(target);

        // ---- Phase D: reduce2 -> h_new, emit history ----
        {
            int e = bx * 256 + tid;
            float4 c = ((const float4*)g_xi)[(size_t)t * (BB * LL / 4) + e];
            const float4* P = (const float4*)g_p2;
#pragma unroll
            for (int k = 0; k < 16; k++) {
                float4 p = P[(size_t)k * 32768 + e];
                c.x += p.x; c.y += p.y; c.z += p.z; c.w += p.w;
            }
            float4 z = ((const float4*)g_z)[e];
            float4 h = ((const float4*)g_h)[e];
            float4 hn;
            hn.x = (1.f - z.x) * h.x + z.x * tanhf(c.x);
            hn.y = (1.f - z.y) * h.y + z.y * tanhf(c.y);
            hn.z = (1.f - z.z) * h.z + z.z * tanhf(c.z);
            hn.w = (1.f - z.w) * h.w + z.w * tanhf(c.w);
            ((float4*)g_h)[e] = hn;
            ((float4*)out)[(size_t)t * (BB * LL / 4) + e] = hn;
        }
        target += NB; grid_sync(target);
    }

    // exit protocol: last CTA resets barrier counters
    if (tid == 0) {
        __threadfence();
        unsigned done = atomicAdd(&g_bar2, 1u) + 1;
        if (done == NB) {
            g_bar1 = 0;
            g_bar2 = 0;
            __threadfence();
        }
    }
}

extern "C" void kernel_launch(void* const* d_in, const int* in_sizes, int n_in,
                              void* d_out, int out_size) {
    const float* x  = (const float*)d_in[0];
    const float* Wz = (const float*)d_in[1];
    const float* bz = (const float*)d_in[2];
    const float* Wr = (const float*)d_in[3];
    const float* br = (const float*)d_in[4];
    const float* Wi = (const float*)d_in[5];
    const float* bi = (const float*)d_in[6];
    float* out = (float*)d_out;

    cudaFuncSetAttribute(xproj_kernel, cudaFuncAttributeMaxDynamicSharedMemorySize, XP_SMEM);
    cudaFuncSetAttribute(gru_persistent, cudaFuncAttributeMaxDynamicSharedMemorySize, PR_SMEM);

    xproj_kernel<<<dim3(24, 256), 256, XP_SMEM>>>(x, Wz, bz, Wr, br, Wi, bi);
    gru_persistent<<<NB, 256, PR_SMEM>>>(Wz, Wr, Wi, out);
}

// round 6
// speedup vs baseline: 1.7041x; 1.0417x over previous
#include <cuda_runtime.h>
#include <cuda_bf16.h>
#include <math.h>

#define BB 128
#define TT 256
#define DD 512
#define LL 1024
#define NB 128   // persistent grid size (<=148 SMs -> co-resident)

// ---------- scratch (static device memory; no allocations) ----------
__device__ __align__(16) float g_xz[TT * BB * LL];   // x @ Wz_x^T + bz, [t][b][l]
__device__ __align__(16) float g_xr[TT * BB * LL];
__device__ __align__(16) float g_xi[TT * BB * LL];
__device__ __align__(16) float g_h [BB * LL];        // current hidden
__device__ __align__(16) float g_z [BB * LL];        // update gate for current step
__device__ __align__(16) float g_rh[BB * LL];        // r * h for current step
__device__ __align__(16) float g_p1[8  * BB * 2048]; // K-split partials, phase 1
__device__ __align__(16) float g_p2[16 * BB * LL];   // K-split partials, phase 2
__device__ unsigned g_bar1 = 0;
__device__ unsigned g_bar2 = 0;

// ---- software grid barrier (persistent kernel) ----
__device__ __forceinline__ void grid_sync(unsigned target) {
    __syncthreads();
    if (threadIdx.x == 0) {
        __threadfence();
        atomicAdd(&g_bar1, 1u);
        unsigned v;
        do {
            asm volatile("ld.acquire.gpu.u32 %0, [%1];" : "=r"(v) : "l"(&g_bar1));
        } while (v < target);
    }
    __syncthreads();
}

// ---- portable tensor-core primitives ----
__device__ __forceinline__ unsigned smem_u32(const void* p) {
    unsigned a;
    asm("{ .reg .u64 t; cvta.to.shared.u64 t, %1; cvt.u32.u64 %0, t; }" : "=r"(a) : "l"(p));
    return a;
}
__device__ __forceinline__ void ldsm4(unsigned (&r)[4], unsigned addr) {
    asm volatile("ldmatrix.sync.aligned.m8n8.x4.shared.b16 {%0,%1,%2,%3}, [%4];"
                 : "=r"(r[0]), "=r"(r[1]), "=r"(r[2]), "=r"(r[3]) : "r"(addr));
}
__device__ __forceinline__ void mma16816(float (&d)[4], const unsigned (&a)[4],
                                         unsigned b0, unsigned b1) {
    asm volatile("mma.sync.aligned.m16n8k16.row.col.f32.bf16.bf16.f32 "
                 "{%0,%1,%2,%3}, {%4,%5,%6,%7}, {%8,%9}, {%0,%1,%2,%3};"
                 : "+f"(d[0]), "+f"(d[1]), "+f"(d[2]), "+f"(d[3])
                 : "r"(a[0]), "r"(a[1]), "r"(a[2]), "r"(a[3]), "r"(b0), "r"(b1));
}

// ---- fp32 -> (bf16 hi, bf16 lo) split-stage into padded-row smem tile ----
// 512 threads, 128 rows, 4 threads per row. Row stride SST bf16 elements.
template<int WIDTH, int SST>
__device__ __forceinline__ void stage_pad(char* __restrict__ hiB, char* __restrict__ loB,
                                          const float* __restrict__ src, int srcStride, int c0)
{
    int tid = threadIdx.x;
    int r = tid >> 2, part = tid & 3;
    const int CH = WIDTH / 4;
    int kl0 = part * CH;
    const float* s = src + (size_t)r * srcStride + c0 + kl0;
    unsigned short* hp = (unsigned short*)hiB + r * SST + kl0;
    unsigned short* lp = (unsigned short*)loB + r * SST + kl0;
#pragma unroll
    for (int g = 0; g < CH / 8; g++) {
        float4 f0 = *(const float4*)(s + g * 8);
        float4 f1 = *(const float4*)(s + g * 8 + 4);
        float xs[8] = {f0.x, f0.y, f0.z, f0.w, f1.x, f1.y, f1.z, f1.w};
        unsigned hu[4], lu[4];
#pragma unroll
        for (int p = 0; p < 4; p++) {
            __nv_bfloat16 h0 = __float2bfloat16(xs[2 * p]);
            __nv_bfloat16 h1 = __float2bfloat16(xs[2 * p + 1]);
            float l0 = xs[2 * p]     - __bfloat162float(h0);
            float l1 = xs[2 * p + 1] - __bfloat162float(h1);
            __nv_bfloat16 lb0 = __float2bfloat16(l0);
            __nv_bfloat16 lb1 = __float2bfloat16(l1);
            hu[p] = (unsigned)__bfloat16_as_ushort(h0) | ((unsigned)__bfloat16_as_ushort(h1) << 16);
            lu[p] = (unsigned)__bfloat16_as_ushort(lb0) | ((unsigned)__bfloat16_as_ushort(lb1) << 16);
        }
        *(uint4*)(hp + g * 8) = make_uint4(hu[0], hu[1], hu[2], hu[3]);
        *(uint4*)(lp + g * 8) = make_uint4(lu[0], lu[1], lu[2], lu[3]);
    }
}

// ---- warp-tile GEMM: CTA 128x128, 16 warps as 4(m)x4(n), warp tile 32x32 ----
// acc[im][in8][4]: 2 m16 frags x 4 n8 frags. 3-term split-bf16 per k16.
template<int SSTA, int SSTB>
__device__ __forceinline__ void wgemm(unsigned aHi, unsigned aLo,
                                      unsigned bHi, unsigned bLo,
                                      int ksteps, float (&acc)[2][4][4])
{
    int lane = threadIdx.x & 31, wid = threadIdx.x >> 5;
    int m0w = (wid & 3) * 32, n0w = (wid >> 2) * 32;
    unsigned aoff = ((m0w + (lane & 15)) * SSTA + ((lane >> 4) << 3)) * 2;
    unsigned boff = ((n0w + (lane & 7) + ((lane >> 4) & 1) * 8) * SSTB
                     + (((lane >> 3) & 1) << 3)) * 2;
    for (int ks = 0; ks < ksteps; ks++) {
        unsigned ka = aoff + ks * 32, kb = boff + ks * 32;
        unsigned bh[2][4], bl[2][4];
        ldsm4(bh[0], bHi + kb);
        ldsm4(bh[1], bHi + kb + 16 * SSTB * 2);
        ldsm4(bl[0], bLo + kb);
        ldsm4(bl[1], bLo + kb + 16 * SSTB * 2);
#pragma unroll
        for (int im = 0; im < 2; im++) {
            unsigned ah[4], al[4];
            ldsm4(ah, aHi + ka + im * 16 * SSTA * 2);
            ldsm4(al, aLo + ka + im * 16 * SSTA * 2);
#pragma unroll
            for (int ib = 0; ib < 2; ib++) {
                mma16816(acc[im][ib * 2 + 0], ah, bh[ib][0], bh[ib][1]);
                mma16816(acc[im][ib * 2 + 1], ah, bh[ib][2], bh[ib][3]);
                mma16816(acc[im][ib * 2 + 0], ah, bl[ib][0], bl[ib][1]);
                mma16816(acc[im][ib * 2 + 1], ah, bl[ib][2], bl[ib][3]);
                mma16816(acc[im][ib * 2 + 0], al, bh[ib][0], bh[ib][1]);
                mma16816(acc[im][ib * 2 + 1], al, bh[ib][2], bh[ib][3]);
            }
        }
    }
}

__device__ __forceinline__ void zero_acc(float (&acc)[2][4][4]) {
#pragma unroll
    for (int i = 0; i < 2; i++)
#pragma unroll
        for (int j = 0; j < 4; j++)
#pragma unroll
            for (int q = 0; q < 4; q++) acc[i][j][q] = 0.f;
}

// acc -> global fp32 (row stride ldd)
__device__ __forceinline__ void store_acc(float* __restrict__ dst, int ldd,
                                          const float (&acc)[2][4][4])
{
    int lane = threadIdx.x & 31, wid = threadIdx.x >> 5;
    int m0w = (wid & 3) * 32, n0w = (wid >> 2) * 32;
    int r = lane >> 2, cp = (lane & 3) * 2;
#pragma unroll
    for (int im = 0; im < 2; im++)
#pragma unroll
        for (int in8 = 0; in8 < 4; in8++) {
            float* p = dst + (size_t)(m0w + im * 16 + r) * ldd + n0w + in8 * 8 + cp;
            *(float2*)p = make_float2(acc[im][in8][0], acc[im][in8][1]);
            *(float2*)(p + 8 * ldd) = make_float2(acc[im][in8][2], acc[im][in8][3]);
        }
}

// ================= xproj: x @ W_x^T + b, tensor cores =================
// grid (24, 256): 24 n-tiles (3 gates x 8), 256 m-tiles of 128 over B*T.
#define XSST 72
#define XTB  18432
#define XP_SMEM (4 * XTB)

__global__ void __launch_bounds__(512) xproj_kernel(
    const float* __restrict__ x,
    const float* __restrict__ Wz, const float* __restrict__ bz,
    const float* __restrict__ Wr, const float* __restrict__ br,
    const float* __restrict__ Wi, const float* __restrict__ bi)
{
    extern __shared__ char smb[];
    __shared__ float sbias[128];
    char* AH = smb;
    char* AL = smb + XTB;
    char* WH = smb + 2 * XTB;
    char* WL = smb + 3 * XTB;

    int tid = threadIdx.x;
    int g = blockIdx.x >> 3;
    int n0 = (blockIdx.x & 7) * 128;
    int m0 = blockIdx.y * 128;
    const float* W    = (g == 0) ? Wz : ((g == 1) ? Wr : Wi);
    const float* bias = (g == 0) ? bz : ((g == 1) ? br : bi);
    float* Xg         = (g == 0) ? g_xz : ((g == 1) ? g_xr : g_xi);

    if (tid < 128) sbias[tid] = bias[n0 + tid];

    unsigned aHi = smem_u32(AH), aLo = smem_u32(AL);
    unsigned bHi = smem_u32(WH), bLo = smem_u32(WL);

    float acc[2][4][4];
    zero_acc(acc);

    for (int c = 0; c < 8; c++) {           // K=512 in 8 chunks of 64
        int k0 = c * 64;
        stage_pad<64, XSST>(AH, AL, x + (size_t)m0 * DD, DD, k0);
        stage_pad<64, XSST>(WH, WL, W + (size_t)n0 * 1536, 1536, k0);
        __syncthreads();
        wgemm<XSST, XSST>(aHi, aLo, bHi, bLo, 4, acc);
        __syncthreads();
    }

    // epilogue: bias + scatter to [t][b][l]
    int lane = tid & 31, wid = tid >> 5;
    int m0w = (wid & 3) * 32, n0w = (wid >> 2) * 32;
    int r = lane >> 2, cp = (lane & 3) * 2;
#pragma unroll
    for (int im = 0; im < 2; im++) {
#pragma unroll
        for (int in8 = 0; in8 < 4; in8++) {
            int col = n0w + in8 * 8 + cp;
            float b0 = sbias[col], b1 = sbias[col + 1];
            int m = m0 + m0w + im * 16 + r;
            int t = m & 255, b = m >> 8;
            float* p = Xg + (size_t)t * (BB * LL) + (size_t)b * LL + n0 + col;
            *(float2*)p = make_float2(acc[im][in8][0] + b0, acc[im][in8][1] + b1);
            int m2 = m + 8;
            int t2 = m2 & 255, b2 = m2 >> 8;
            float* p2 = Xg + (size_t)t2 * (BB * LL) + (size_t)b2 * LL + n0 + col;
            *(float2*)p2 = make_float2(acc[im][in8][2] + b0, acc[im][in8][3] + b1);
        }
    }
}

// ================= persistent recurrence (tensor cores) =================
// smem (bytes): AT hi/lo 128x136 (34816 each), WA hi/lo 128x136, WC hi/lo 128x72 (18432)
#define ASST 136
#define CSST 72
#define PR_AT_HI 0
#define PR_AT_LO 34816
#define PR_WA_HI 69632
#define PR_WA_LO 104448
#define PR_WC_HI 139264
#define PR_WC_LO 157696
#define PR_SMEM  176128

__global__ void __launch_bounds__(512) gru_persistent(
    const float* __restrict__ Wz, const float* __restrict__ Wr,
    const float* __restrict__ Wi, float* __restrict__ out)
{
    extern __shared__ char smb[];
    int tid = threadIdx.x;
    int bx = blockIdx.x;
    unsigned target = 0;

    unsigned atHi = smem_u32(smb + PR_AT_HI), atLo = smem_u32(smb + PR_AT_LO);
    unsigned waHi = smem_u32(smb + PR_WA_HI), waLo = smem_u32(smb + PR_WA_LO);
    unsigned wcHi = smem_u32(smb + PR_WC_HI), wcLo = smem_u32(smb + PR_WC_LO);

    // CTA roles
    int kidxA = bx >> 4;            // 0..7  (phase-A K-slice of 128)
    int n0A   = (bx & 15) * 128;    // over N=2048
    int kidxC = bx >> 3;            // 0..15 (phase-C K-slice of 64)
    int n0C   = (bx & 7) * 128;     // over N=1024

    // one-time: weight slices -> smem bf16 hi/lo (reused for all 256 steps)
    {
        const float* wbA = (n0A < 1024) ? Wz + (size_t)n0A * 1536
                                        : Wr + (size_t)(n0A - 1024) * 1536;
        stage_pad<128, ASST>(smb + PR_WA_HI, smb + PR_WA_LO, wbA, 1536, 512 + kidxA * 128);
        stage_pad<64, CSST>(smb + PR_WC_HI, smb + PR_WC_LO,
                            Wi + (size_t)n0C * 1536, 1536, 512 + kidxC * 64);
    }
    // init h = 0 (65536 float2 across 128*512 threads)
    {
        int e2 = bx * 512 + tid;
        ((float2*)g_h)[e2] = make_float2(0.f, 0.f);
    }
    target += NB; grid_sync(target);

    for (int t = 0; t < TT; ++t) {
        // ---- Phase A: h @ [Wzh | Wrh]^T partials (K-slice 128) ----
        {
            stage_pad<128, ASST>(smb + PR_AT_HI, smb + PR_AT_LO, g_h, LL, kidxA * 128);
            __syncthreads();
            float acc[2][4][4];
            zero_acc(acc);
            wgemm<ASST, ASST>(atHi, atLo, waHi, waLo, 8, acc);
            store_acc(g_p1 + (size_t)kidxA * BB * 2048 + n0A, 2048, acc);
        }
        target += NB; grid_sync(target);

        // ---- Phase B: reduce1 -> z, rh (float2 per thread) ----
        {
            int e2 = bx * 512 + tid;         // float2 index over [B][L], 65536 total
            int b = e2 >> 9, l2 = e2 & 511;
            const float2* P = (const float2*)g_p1;
            float2 zs = ((const float2*)g_xz)[(size_t)t * 65536 + e2];
            float2 rs = ((const float2*)g_xr)[(size_t)t * 65536 + e2];
#pragma unroll
            for (int k = 0; k < 8; k++) {
                float2 pz = P[(size_t)k * 131072 + b * 1024 + l2];
                float2 pr = P[(size_t)k * 131072 + b * 1024 + 512 + l2];
                zs.x += pz.x; zs.y += pz.y;
                rs.x += pr.x; rs.y += pr.y;
            }
            float2 z, r;
            z.x = 1.f / (1.f + __expf(-zs.x)); z.y = 1.f / (1.f + __expf(-zs.y));
            r.x = 1.f / (1.f + __expf(-rs.x)); r.y = 1.f / (1.f + __expf(-rs.y));
            float2 h = ((const float2*)g_h)[e2];
            ((float2*)g_z)[e2] = z;
            ((float2*)g_rh)[e2] = make_float2(r.x * h.x, r.y * h.y);
        }
        target += NB; grid_sync(target);

        // ---- Phase C: (r*h) @ Wih^T partials (K-slice 64) ----
        {
            stage_pad<64, ASST>(smb + PR_AT_HI, smb + PR_AT_LO, g_rh, LL, kidxC * 64);
            __syncthreads();
            float acc[2][4][4];
            zero_acc(acc);
            wgemm<ASST, CSST>(atHi, atLo, wcHi, wcLo, 4, acc);
            store_acc(g_p2 + (size_t)kidxC * BB * LL + n0C, 1024, acc);
        }
        target += NB; grid_sync(target);

        // ---- Phase D: reduce2 -> h_new, emit history ----
        {
            int e2 = bx * 512 + tid;
            float2 c = ((const float2*)g_xi)[(size_t)t * 65536 + e2];
            const float2* P = (const float2*)g_p2;
#pragma unroll
            for (int k = 0; k < 16; k++) {
                float2 p = P[(size_t)k * 65536 + e2];
                c.x += p.x; c.y += p.y;
            }
            float2 z = ((const float2*)g_z)[e2];
            float2 h = ((const float2*)g_h)[e2];
            float2 hn;
            hn.x = (1.f - z.x) * h.x + z.x * tanhf(c.x);
            hn.y = (1.f - z.y) * h.y + z.y * tanhf(c.y);
            ((float2*)g_h)[e2] = hn;
            ((float2*)out)[(size_t)t * 65536 + e2] = hn;
        }
        target += NB; grid_sync(target);
    }

    // exit protocol: last CTA resets barrier counters
    if (tid == 0) {
        __threadfence();
        unsigned done = atomicAdd(&g_bar2, 1u) + 1;
        if (done == NB) {
            g_bar1 = 0;
            g_bar2 = 0;
            __threadfence();
        }
    }
}

extern "C" void kernel_launch(void* const* d_in, const int* in_sizes, int n_in,
                              void* d_out, int out_size) {
    const float* x  = (const float*)d_in[0];
    const float* Wz = (const float*)d_in[1];
    const float* bz = (const float*)d_in[2];
    const float* Wr = (const float*)d_in[3];
    const float* br = (const float*)d_in[4];
    const float* Wi = (const float*)d_in[5];
    const float* bi = (const float*)d_in[6];
    float* out = (float*)d_out;

    cudaFuncSetAttribute(xproj_kernel, cudaFuncAttributeMaxDynamicSharedMemorySize, XP_SMEM);
    cudaFuncSetAttribute(gru_persistent, cudaFuncAttributeMaxDynamicSharedMemorySize, PR_SMEM);

    xproj_kernel<<<dim3(24, 256), 512, XP_SMEM>>>(x, Wz, bz, Wr, br, Wi, bi);
    gru_persistent<<<NB, 512, PR_SMEM>>>(Wz, Wr, Wi, out);
}

// round 7
// speedup vs baseline: 1.7076x; 1.0021x over previous
#include <cuda_runtime.h>
#include <cuda_bf16.h>
#include <math.h>

#define BB 128
#define TT 256
#define DD 512
#define LL 1024
#define NB 128   // persistent grid size (<=148 SMs -> co-resident)

// ---------- scratch (static device memory; no allocations) ----------
__device__ __align__(16) float g_xz[TT * BB * LL];   // x @ Wz_x^T + bz, [t][b][l]
__device__ __align__(16) float g_xr[TT * BB * LL];
__device__ __align__(16) float g_xi[TT * BB * LL];
__device__ __align__(16) float g_h [BB * LL];        // current hidden
__device__ __align__(16) float g_z [BB * LL];        // update gate for current step
__device__ __align__(16) float g_rh[BB * LL];        // r * h for current step
__device__ __align__(16) float g_p1[8  * BB * 2048]; // K-split partials, phase 1
__device__ __align__(16) float g_p2[16 * BB * LL];   // K-split partials, phase 2
__device__ unsigned g_bar1 = 0;
__device__ unsigned g_bar2 = 0;

// ---- software grid barrier (persistent kernel) ----
__device__ __forceinline__ void grid_sync(unsigned target) {
    __syncthreads();
    if (threadIdx.x == 0) {
        __threadfence();
        atomicAdd(&g_bar1, 1u);
        unsigned v;
        do {
            asm volatile("ld.acquire.gpu.u32 %0, [%1];" : "=r"(v) : "l"(&g_bar1));
        } while (v < target);
    }
    __syncthreads();
}

// ---- portable tensor-core primitives ----
__device__ __forceinline__ unsigned smem_u32(const void* p) {
    unsigned a;
    asm("{ .reg .u64 t; cvta.to.shared.u64 t, %1; cvt.u32.u64 %0, t; }" : "=r"(a) : "l"(p));
    return a;
}
__device__ __forceinline__ void ldsm4(unsigned (&r)[4], unsigned addr) {
    asm volatile("ldmatrix.sync.aligned.m8n8.x4.shared.b16 {%0,%1,%2,%3}, [%4];"
                 : "=r"(r[0]), "=r"(r[1]), "=r"(r[2]), "=r"(r[3]) : "r"(addr));
}
__device__ __forceinline__ void mma16816(float (&d)[4], const unsigned (&a)[4],
                                         unsigned b0, unsigned b1) {
    asm volatile("mma.sync.aligned.m16n8k16.row.col.f32.bf16.bf16.f32 "
                 "{%0,%1,%2,%3}, {%4,%5,%6,%7}, {%8,%9}, {%0,%1,%2,%3};"
                 : "+f"(d[0]), "+f"(d[1]), "+f"(d[2]), "+f"(d[3])
                 : "r"(a[0]), "r"(a[1]), "r"(a[2]), "r"(a[3]), "r"(b0), "r"(b1));
}

// ---- fp32 -> (bf16 hi, bf16 lo) split-stage into padded-row smem tile ----
// 512 threads, 128 rows, 4 threads per row. Row stride SST bf16 elements.
template<int WIDTH, int SST>
__device__ __forceinline__ void stage_pad(char* __restrict__ hiB, char* __restrict__ loB,
                                          const float* __restrict__ src, int srcStride, int c0)
{
    int tid = threadIdx.x;
    int r = tid >> 2, part = tid & 3;
    const int CH = WIDTH / 4;
    int kl0 = part * CH;
    const float* s = src + (size_t)r * srcStride + c0 + kl0;
    unsigned short* hp = (unsigned short*)hiB + r * SST + kl0;
    unsigned short* lp = (unsigned short*)loB + r * SST + kl0;
#pragma unroll
    for (int g = 0; g < CH / 8; g++) {
        float4 f0 = *(const float4*)(s + g * 8);
        float4 f1 = *(const float4*)(s + g * 8 + 4);
        float xs[8] = {f0.x, f0.y, f0.z, f0.w, f1.x, f1.y, f1.z, f1.w};
        unsigned hu[4], lu[4];
#pragma unroll
        for (int p = 0; p < 4; p++) {
            __nv_bfloat16 h0 = __float2bfloat16(xs[2 * p]);
            __nv_bfloat16 h1 = __float2bfloat16(xs[2 * p + 1]);
            float l0 = xs[2 * p]     - __bfloat162float(h0);
            float l1 = xs[2 * p + 1] - __bfloat162float(h1);
            __nv_bfloat16 lb0 = __float2bfloat16(l0);
            __nv_bfloat16 lb1 = __float2bfloat16(l1);
            hu[p] = (unsigned)__bfloat16_as_ushort(h0) | ((unsigned)__bfloat16_as_ushort(h1) << 16);
            lu[p] = (unsigned)__bfloat16_as_ushort(lb0) | ((unsigned)__bfloat16_as_ushort(lb1) << 16);
        }
        *(uint4*)(hp + g * 8) = make_uint4(hu[0], hu[1], hu[2], hu[3]);
        *(uint4*)(lp + g * 8) = make_uint4(lu[0], lu[1], lu[2], lu[3]);
    }
}

// ---- warp-tile GEMM: CTA 128x128, 16 warps as 4(m)x4(n), warp tile 32x32 ----
// acc[im][in8][4]: 2 m16 frags x 4 n8 frags. 3-term split-bf16 per k16.
template<int SSTA, int SSTB>
__device__ __forceinline__ void wgemm(unsigned aHi, unsigned aLo,
                                      unsigned bHi, unsigned bLo,
                                      int ksteps, float (&acc)[2][4][4])
{
    int lane = threadIdx.x & 31, wid = threadIdx.x >> 5;
    int m0w = (wid & 3) * 32, n0w = (wid >> 2) * 32;
    unsigned aoff = ((m0w + (lane & 15)) * SSTA + ((lane >> 4) << 3)) * 2;
    unsigned boff = ((n0w + (lane & 7) + ((lane >> 4) & 1) * 8) * SSTB
                     + (((lane >> 3) & 1) << 3)) * 2;
    for (int ks = 0; ks < ksteps; ks++) {
        unsigned ka = aoff + ks * 32, kb = boff + ks * 32;
        unsigned bh[2][4], bl[2][4];
        ldsm4(bh[0], bHi + kb);
        ldsm4(bh[1], bHi + kb + 16 * SSTB * 2);
        ldsm4(bl[0], bLo + kb);
        ldsm4(bl[1], bLo + kb + 16 * SSTB * 2);
#pragma unroll
        for (int im = 0; im < 2; im++) {
            unsigned ah[4], al[4];
            ldsm4(ah, aHi + ka + im * 16 * SSTA * 2);
            ldsm4(al, aLo + ka + im * 16 * SSTA * 2);
#pragma unroll
            for (int ib = 0; ib < 2; ib++) {
                mma16816(acc[im][ib * 2 + 0], ah, bh[ib][0], bh[ib][1]);
                mma16816(acc[im][ib * 2 + 1], ah, bh[ib][2], bh[ib][3]);
                mma16816(acc[im][ib * 2 + 0], ah, bl[ib][0], bl[ib][1]);
                mma16816(acc[im][ib * 2 + 1], ah, bl[ib][2], bl[ib][3]);
                mma16816(acc[im][ib * 2 + 0], al, bh[ib][0], bh[ib][1]);
                mma16816(acc[im][ib * 2 + 1], al, bh[ib][2], bh[ib][3]);
            }
        }
    }
}

__device__ __forceinline__ void zero_acc(float (&acc)[2][4][4]) {
#pragma unroll
    for (int i = 0; i < 2; i++)
#pragma unroll
        for (int j = 0; j < 4; j++)
#pragma unroll
            for (int q = 0; q < 4; q++) acc[i][j][q] = 0.f;
}

// acc -> global fp32 (row stride ldd)
__device__ __forceinline__ void store_acc(float* __restrict__ dst, int ldd,
                                          const float (&acc)[2][4][4])
{
    int lane = threadIdx.x & 31, wid = threadIdx.x >> 5;
    int m0w = (wid & 3) * 32, n0w = (wid >> 2) * 32;
    int r = lane >> 2, cp = (lane & 3) * 2;
#pragma unroll
    for (int im = 0; im < 2; im++)
#pragma unroll
        for (int in8 = 0; in8 < 4; in8++) {
            float* p = dst + (size_t)(m0w + im * 16 + r) * ldd + n0w + in8 * 8 + cp;
            *(float2*)p = make_float2(acc[im][in8][0], acc[im][in8][1]);
            *(float2*)(p + 8 * ldd) = make_float2(acc[im][in8][2], acc[im][in8][3]);
        }
}

// ================= xproj: x @ W_x^T + b, tensor cores =================
// grid (24, 256): 24 n-tiles (3 gates x 8), 256 m-tiles of 128 over B*T.
#define XSST 72
#define XTB  18432
#define XP_SMEM (4 * XTB)

__global__ void __launch_bounds__(512) xproj_kernel(
    const float* __restrict__ x,
    const float* __restrict__ Wz, const float* __restrict__ bz,
    const float* __restrict__ Wr, const float* __restrict__ br,
    const float* __restrict__ Wi, const float* __restrict__ bi)
{
    extern __shared__ char smb[];
    __shared__ float sbias[128];
    char* AH = smb;
    char* AL = smb + XTB;
    char* WH = smb + 2 * XTB;
    char* WL = smb + 3 * XTB;

    int tid = threadIdx.x;
    int g = blockIdx.x >> 3;
    int n0 = (blockIdx.x & 7) * 128;
    int m0 = blockIdx.y * 128;
    const float* W    = (g == 0) ? Wz : ((g == 1) ? Wr : Wi);
    const float* bias = (g == 0) ? bz : ((g == 1) ? br : bi);
    float* Xg         = (g == 0) ? g_xz : ((g == 1) ? g_xr : g_xi);

    if (tid < 128) sbias[tid] = bias[n0 + tid];

    unsigned aHi = smem_u32(AH), aLo = smem_u32(AL);
    unsigned bHi = smem_u32(WH), bLo = smem_u32(WL);

    float acc[2][4][4];
    zero_acc(acc);

    for (int c = 0; c < 8; c++) {           // K=512 in 8 chunks of 64
        int k0 = c * 64;
        stage_pad<64, XSST>(AH, AL, x + (size_t)m0 * DD, DD, k0);
        stage_pad<64, XSST>(WH, WL, W + (size_t)n0 * 1536, 1536, k0);
        __syncthreads();
        wgemm<XSST, XSST>(aHi, aLo, bHi, bLo, 4, acc);
        __syncthreads();
    }

    // epilogue: bias + scatter to [t][b][l]
    int lane = tid & 31, wid = tid >> 5;
    int m0w = (wid & 3) * 32, n0w = (wid >> 2) * 32;
    int r = lane >> 2, cp = (lane & 3) * 2;
#pragma unroll
    for (int im = 0; im < 2; im++) {
#pragma unroll
        for (int in8 = 0; in8 < 4; in8++) {
            int col = n0w + in8 * 8 + cp;
            float b0 = sbias[col], b1 = sbias[col + 1];
            int m = m0 + m0w + im * 16 + r;
            int t = m & 255, b = m >> 8;
            float* p = Xg + (size_t)t * (BB * LL) + (size_t)b * LL + n0 + col;
            *(float2*)p = make_float2(acc[im][in8][0] + b0, acc[im][in8][1] + b1);
            int m2 = m + 8;
            int t2 = m2 & 255, b2 = m2 >> 8;
            float* p2 = Xg + (size_t)t2 * (BB * LL) + (size_t)b2 * LL + n0 + col;
            *(float2*)p2 = make_float2(acc[im][in8][2] + b0, acc[im][in8][3] + b1);
        }
    }
}

// ================= persistent recurrence (tensor cores) =================
// smem (bytes): AT hi/lo 128x136 (34816 each), WA hi/lo 128x136, WC hi/lo 128x72 (18432)
#define ASST 136
#define CSST 72
#define PR_AT_HI 0
#define PR_AT_LO 34816
#define PR_WA_HI 69632
#define PR_WA_LO 104448
#define PR_WC_HI 139264
#define PR_WC_LO 157696
#define PR_SMEM  176128

__global__ void __launch_bounds__(512) gru_persistent(
    const float* __restrict__ Wz, const float* __restrict__ Wr,
    const float* __restrict__ Wi, float* __restrict__ out)
{
    extern __shared__ char smb[];
    int tid = threadIdx.x;
    int bx = blockIdx.x;
    unsigned target = 0;

    unsigned atHi = smem_u32(smb + PR_AT_HI), atLo = smem_u32(smb + PR_AT_LO);
    unsigned waHi = smem_u32(smb + PR_WA_HI), waLo = smem_u32(smb + PR_WA_LO);
    unsigned wcHi = smem_u32(smb + PR_WC_HI), wcLo = smem_u32(smb + PR_WC_LO);

    // CTA roles
    int kidxA = bx >> 4;            // 0..7  (phase-A K-slice of 128)
    int n0A   = (bx & 15) * 128;    // over N=2048
    int kidxC = bx >> 3;            // 0..15 (phase-C K-slice of 64)
    int n0C   = (bx & 7) * 128;     // over N=1024

    // one-time: weight slices -> smem bf16 hi/lo (reused for all 256 steps)
    {
        const float* wbA = (n0A < 1024) ? Wz + (size_t)n0A * 1536
                                        : Wr + (size_t)(n0A - 1024) * 1536;
        stage_pad<128, ASST>(smb + PR_WA_HI, smb + PR_WA_LO, wbA, 1536, 512 + kidxA * 128);
        stage_pad<64, CSST>(smb + PR_WC_HI, smb + PR_WC_LO,
                            Wi + (size_t)n0C * 1536, 1536, 512 + kidxC * 64);
    }
    // init h = 0 (65536 float2 across 128*512 threads)
    {
        int e2 = bx * 512 + tid;
        ((float2*)g_h)[e2] = make_float2(0.f, 0.f);
    }
    target += NB; grid_sync(target);

    for (int t = 0; t < TT; ++t) {
        // ---- Phase A: h @ [Wzh | Wrh]^T partials (K-slice 128) ----
        {
            stage_pad<128, ASST>(smb + PR_AT_HI, smb + PR_AT_LO, g_h, LL, kidxA * 128);
            __syncthreads();
            float acc[2][4][4];
            zero_acc(acc);
            wgemm<ASST, ASST>(atHi, atLo, waHi, waLo, 8, acc);
            store_acc(g_p1 + (size_t)kidxA * BB * 2048 + n0A, 2048, acc);
        }
        target += NB; grid_sync(target);

        // ---- Phase B: reduce1 -> z, rh (float2 per thread) ----
        {
            int e2 = bx * 512 + tid;         // float2 index over [B][L], 65536 total
            int b = e2 >> 9, l2 = e2 & 511;
            const float2* P = (const float2*)g_p1;
            float2 zs = ((const float2*)g_xz)[(size_t)t * 65536 + e2];
            float2 rs = ((const float2*)g_xr)[(size_t)t * 65536 + e2];
#pragma unroll
            for (int k = 0; k < 8; k++) {
                float2 pz = P[(size_t)k * 131072 + b * 1024 + l2];
                float2 pr = P[(size_t)k * 131072 + b * 1024 + 512 + l2];
                zs.x += pz.x; zs.y += pz.y;
                rs.x += pr.x; rs.y += pr.y;
            }
            float2 z, r;
            z.x = 1.f / (1.f + __expf(-zs.x)); z.y = 1.f / (1.f + __expf(-zs.y));
            r.x = 1.f / (1.f + __expf(-rs.x)); r.y = 1.f / (1.f + __expf(-rs.y));
            float2 h = ((const float2*)g_h)[e2];
            ((float2*)g_z)[e2] = z;
            ((float2*)g_rh)[e2] = make_float2(r.x * h.x, r.y * h.y);
        }
        target += NB; grid_sync(target);

        // ---- Phase C: (r*h) @ Wih^T partials (K-slice 64) ----
        {
            stage_pad<64, ASST>(smb + PR_AT_HI, smb + PR_AT_LO, g_rh, LL, kidxC * 64);
            __syncthreads();
            float acc[2][4][4];
            zero_acc(acc);
            wgemm<ASST, CSST>(atHi, atLo, wcHi, wcLo, 4, acc);
            store_acc(g_p2 + (size_t)kidxC * BB * LL + n0C, 1024, acc);
        }
        target += NB; grid_sync(target);

        // ---- Phase D: reduce2 -> h_new, emit history ----
        {
            int e2 = bx * 512 + tid;
            float2 c = ((const float2*)g_xi)[(size_t)t * 65536 + e2];
            const float2* P = (const float2*)g_p2;
#pragma unroll
            for (int k = 0; k < 16; k++) {
                float2 p = P[(size_t)k * 65536 + e2];
                c.x += p.x; c.y += p.y;
            }
            float2 z = ((const float2*)g_z)[e2];
            float2 h = ((const float2*)g_h)[e2];
            float2 hn;
            hn.x = (1.f - z.x) * h.x + z.x * tanhf(c.x);
            hn.y = (1.f - z.y) * h.y + z.y * tanhf(c.y);
            ((float2*)g_h)[e2] = hn;
            ((float2*)out)[(size_t)t * 65536 + e2] = hn;
        }
        target += NB; grid_sync(target);
    }

    // exit protocol: last CTA resets barrier counters
    if (tid == 0) {
        __threadfence();
        unsigned done = atomicAdd(&g_bar2, 1u) + 1;
        if (done == NB) {
            g_bar1 = 0;
            g_bar2 = 0;
            __threadfence();
        }
    }
}

extern "C" void kernel_launch(void* const* d_in, const int* in_sizes, int n_in,
                              void* d_out, int out_size) {
    const float* x  = (const float*)d_in[0];
    const float* Wz = (const float*)d_in[1];
    const float* bz = (const float*)d_in[2];
    const float* Wr = (const float*)d_in[3];
    const float* br = (const float*)d_in[4];
    const float* Wi = (const float*)d_in[5];
    const float* bi = (const float*)d_in[6];
    float* out = (float*)d_out;

    cudaFuncSetAttribute(xproj_kernel, cudaFuncAttributeMaxDynamicSharedMemorySize, XP_SMEM);
    cudaFuncSetAttribute(gru_persistent, cudaFuncAttributeMaxDynamicSharedMemorySize, PR_SMEM);

    xproj_kernel<<<dim3(24, 256), 512, XP_SMEM>>>(x, Wz, bz, Wr, br, Wi, bi);
    gru_persistent<<<NB, 512, PR_SMEM>>>(Wz, Wr, Wi, out);
}

// round 8
// speedup vs baseline: 1.8433x; 1.0795x over previous
#include <cuda_runtime.h>
#include <cuda_bf16.h>
#include <math.h>

#define BB 128
#define TT 256
#define DD 512
#define LL 1024
#define NB 128   // persistent grid size (<=148 SMs -> co-resident)

// ---------- scratch (static device memory; no allocations) ----------
__device__ __align__(16) float g_xz[TT * BB * LL];   // x @ Wz_x^T + bz, [t][b][l]
__device__ __align__(16) float g_xr[TT * BB * LL];
__device__ __align__(16) float g_xi[TT * BB * LL];
__device__ __align__(16) __nv_bfloat16 g_hh[BB * LL];   // h split: hi
__device__ __align__(16) __nv_bfloat16 g_hl[BB * LL];   // h split: lo
__device__ __align__(16) __nv_bfloat16 g_rhh[BB * LL];  // r*h split: hi
__device__ __align__(16) __nv_bfloat16 g_rhl[BB * LL];  // r*h split: lo
__device__ __align__(16) float g_p1[8  * BB * 2048]; // K-split partials, phase 1
__device__ __align__(16) float g_p2[16 * BB * LL];   // K-split partials, phase 2
__device__ unsigned g_bar1 = 0;
__device__ unsigned g_bar2 = 0;

// ---- software grid barrier (persistent kernel) ----
__device__ __forceinline__ void grid_sync(unsigned target) {
    __syncthreads();
    if (threadIdx.x == 0) {
        __threadfence();
        atomicAdd(&g_bar1, 1u);
        unsigned v;
        do {
            asm volatile("ld.acquire.gpu.u32 %0, [%1];" : "=r"(v) : "l"(&g_bar1));
        } while (v < target);
    }
    __syncthreads();
}

// ---- portable tensor-core primitives ----
__device__ __forceinline__ unsigned smem_u32(const void* p) {
    unsigned a;
    asm("{ .reg .u64 t; cvta.to.shared.u64 t, %1; cvt.u32.u64 %0, t; }" : "=r"(a) : "l"(p));
    return a;
}
__device__ __forceinline__ void ldsm4(unsigned (&r)[4], unsigned addr) {
    asm volatile("ldmatrix.sync.aligned.m8n8.x4.shared.b16 {%0,%1,%2,%3}, [%4];"
                 : "=r"(r[0]), "=r"(r[1]), "=r"(r[2]), "=r"(r[3]) : "r"(addr));
}
__device__ __forceinline__ void mma16816(float (&d)[4], const unsigned (&a)[4],
                                         unsigned b0, unsigned b1) {
    asm volatile("mma.sync.aligned.m16n8k16.row.col.f32.bf16.bf16.f32 "
                 "{%0,%1,%2,%3}, {%4,%5,%6,%7}, {%8,%9}, {%0,%1,%2,%3};"
                 : "+f"(d[0]), "+f"(d[1]), "+f"(d[2]), "+f"(d[3])
                 : "r"(a[0]), "r"(a[1]), "r"(a[2]), "r"(a[3]), "r"(b0), "r"(b1));
}

// ---- split/pack helpers ----
__device__ __forceinline__ unsigned pack_bf2(float a, float b) {
    return (unsigned)__bfloat16_as_ushort(__float2bfloat16(a)) |
           ((unsigned)__bfloat16_as_ushort(__float2bfloat16(b)) << 16);
}
__device__ __forceinline__ float bf_lo(unsigned u) {
    return __bfloat162float(__ushort_as_bfloat16((unsigned short)(u & 0xFFFF)));
}
__device__ __forceinline__ float bf_hi(unsigned u) {
    return __bfloat162float(__ushort_as_bfloat16((unsigned short)(u >> 16)));
}

// ---- fp32 -> (bf16 hi, bf16 lo) split-stage into padded-row smem tile ----
// 512 threads, 128 rows, 4 threads per row. Row stride SST bf16 elements.
template<int WIDTH, int SST>
__device__ __forceinline__ void stage_pad(char* __restrict__ hiB, char* __restrict__ loB,
                                          const float* __restrict__ src, int srcStride, int c0)
{
    int tid = threadIdx.x;
    int r = tid >> 2, part = tid & 3;
    const int CH = WIDTH / 4;
    int kl0 = part * CH;
    const float* s = src + (size_t)r * srcStride + c0 + kl0;
    unsigned short* hp = (unsigned short*)hiB + r * SST + kl0;
    unsigned short* lp = (unsigned short*)loB + r * SST + kl0;
#pragma unroll
    for (int g = 0; g < CH / 8; g++) {
        float4 f0 = *(const float4*)(s + g * 8);
        float4 f1 = *(const float4*)(s + g * 8 + 4);
        float xs[8] = {f0.x, f0.y, f0.z, f0.w, f1.x, f1.y, f1.z, f1.w};
        unsigned hu[4], lu[4];
#pragma unroll
        for (int p = 0; p < 4; p++) {
            __nv_bfloat16 h0 = __float2bfloat16(xs[2 * p]);
            __nv_bfloat16 h1 = __float2bfloat16(xs[2 * p + 1]);
            float l0 = xs[2 * p]     - __bfloat162float(h0);
            float l1 = xs[2 * p + 1] - __bfloat162float(h1);
            hu[p] = pack_bf2(__bfloat162float(h0), __bfloat162float(h1));
            lu[p] = pack_bf2(l0, l1);
        }
        *(uint4*)(hp + g * 8) = make_uint4(hu[0], hu[1], hu[2], hu[3]);
        *(uint4*)(lp + g * 8) = make_uint4(lu[0], lu[1], lu[2], lu[3]);
    }
}

// ---- pure-copy stage: split-bf16 gmem arrays -> padded smem (no conversion) ----
#define ASST 136
#define CSST 72
template<int WIDTH>
__device__ __forceinline__ void stage_copy(char* __restrict__ hiB, char* __restrict__ loB,
                                           const __nv_bfloat16* __restrict__ srcH,
                                           const __nv_bfloat16* __restrict__ srcL, int c0)
{
    int tid = threadIdx.x;
    int r = tid >> 2, part = tid & 3;
    const int CH = WIDTH / 4;   // 32 (A) or 16 (C) cols per thread
    const uint4* sH = (const uint4*)(srcH + (size_t)r * LL + c0 + part * CH);
    const uint4* sL = (const uint4*)(srcL + (size_t)r * LL + c0 + part * CH);
    uint4* dH = (uint4*)((unsigned short*)hiB + r * ASST + part * CH);
    uint4* dL = (uint4*)((unsigned short*)loB + r * ASST + part * CH);
#pragma unroll
    for (int i = 0; i < CH / 8; i++) { dH[i] = sH[i]; dL[i] = sL[i]; }
}

// ---- warp-tile GEMM: CTA 128x128, 16 warps as 4(m)x4(n), warp tile 32x32 ----
template<int SSTA, int SSTB>
__device__ __forceinline__ void wgemm(unsigned aHi, unsigned aLo,
                                      unsigned bHi, unsigned bLo,
                                      int ksteps, float (&acc)[2][4][4])
{
    int lane = threadIdx.x & 31, wid = threadIdx.x >> 5;
    int m0w = (wid & 3) * 32, n0w = (wid >> 2) * 32;
    unsigned aoff = ((m0w + (lane & 15)) * SSTA + ((lane >> 4) << 3)) * 2;
    unsigned boff = ((n0w + (lane & 7) + ((lane >> 4) & 1) * 8) * SSTB
                     + (((lane >> 3) & 1) << 3)) * 2;
    for (int ks = 0; ks < ksteps; ks++) {
        unsigned ka = aoff + ks * 32, kb = boff + ks * 32;
        unsigned bh[2][4], bl[2][4];
        ldsm4(bh[0], bHi + kb);
        ldsm4(bh[1], bHi + kb + 16 * SSTB * 2);
        ldsm4(bl[0], bLo + kb);
        ldsm4(bl[1], bLo + kb + 16 * SSTB * 2);
#pragma unroll
        for (int im = 0; im < 2; im++) {
            unsigned ah[4], al[4];
            ldsm4(ah, aHi + ka + im * 16 * SSTA * 2);
            ldsm4(al, aLo + ka + im * 16 * SSTA * 2);
#pragma unroll
            for (int ib = 0; ib < 2; ib++) {
                mma16816(acc[im][ib * 2 + 0], ah, bh[ib][0], bh[ib][1]);
                mma16816(acc[im][ib * 2 + 1], ah, bh[ib][2], bh[ib][3]);
                mma16816(acc[im][ib * 2 + 0], ah, bl[ib][0], bl[ib][1]);
                mma16816(acc[im][ib * 2 + 1], ah, bl[ib][2], bl[ib][3]);
                mma16816(acc[im][ib * 2 + 0], al, bh[ib][0], bh[ib][1]);
                mma16816(acc[im][ib * 2 + 1], al, bh[ib][2], bh[ib][3]);
            }
        }
    }
}

__device__ __forceinline__ void zero_acc(float (&acc)[2][4][4]) {
#pragma unroll
    for (int i = 0; i < 2; i++)
#pragma unroll
        for (int j = 0; j < 4; j++)
#pragma unroll
            for (int q = 0; q < 4; q++) acc[i][j][q] = 0.f;
}

__device__ __forceinline__ void store_acc(float* __restrict__ dst, int ldd,
                                          const float (&acc)[2][4][4])
{
    int lane = threadIdx.x & 31, wid = threadIdx.x >> 5;
    int m0w = (wid & 3) * 32, n0w = (wid >> 2) * 32;
    int r = lane >> 2, cp = (lane & 3) * 2;
#pragma unroll
    for (int im = 0; im < 2; im++)
#pragma unroll
        for (int in8 = 0; in8 < 4; in8++) {
            float* p = dst + (size_t)(m0w + im * 16 + r) * ldd + n0w + in8 * 8 + cp;
            *(float2*)p = make_float2(acc[im][in8][0], acc[im][in8][1]);
            *(float2*)(p + 8 * ldd) = make_float2(acc[im][in8][2], acc[im][in8][3]);
        }
}

// ================= xproj: x @ W_x^T + b, tensor cores (unchanged) =================
#define XSST 72
#define XTB  18432
#define XP_SMEM (4 * XTB)

__global__ void __launch_bounds__(512) xproj_kernel(
    const float* __restrict__ x,
    const float* __restrict__ Wz, const float* __restrict__ bz,
    const float* __restrict__ Wr, const float* __restrict__ br,
    const float* __restrict__ Wi, const float* __restrict__ bi)
{
    extern __shared__ char smb[];
    __shared__ float sbias[128];
    char* AH = smb;
    char* AL = smb + XTB;
    char* WH = smb + 2 * XTB;
    char* WL = smb + 3 * XTB;

    int tid = threadIdx.x;
    int g = blockIdx.x >> 3;
    int n0 = (blockIdx.x & 7) * 128;
    int m0 = blockIdx.y * 128;
    const float* W    = (g == 0) ? Wz : ((g == 1) ? Wr : Wi);
    const float* bias = (g == 0) ? bz : ((g == 1) ? br : bi);
    float* Xg         = (g == 0) ? g_xz : ((g == 1) ? g_xr : g_xi);

    if (tid < 128) sbias[tid] = bias[n0 + tid];

    unsigned aHi = smem_u32(AH), aLo = smem_u32(AL);
    unsigned bHi = smem_u32(WH), bLo = smem_u32(WL);

    float acc[2][4][4];
    zero_acc(acc);

    for (int c = 0; c < 8; c++) {           // K=512 in 8 chunks of 64
        int k0 = c * 64;
        stage_pad<64, XSST>(AH, AL, x + (size_t)m0 * DD, DD, k0);
        stage_pad<64, XSST>(WH, WL, W + (size_t)n0 * 1536, 1536, k0);
        __syncthreads();
        wgemm<XSST, XSST>(aHi, aLo, bHi, bLo, 4, acc);
        __syncthreads();
    }

    int lane = tid & 31, wid = tid >> 5;
    int m0w = (wid & 3) * 32, n0w = (wid >> 2) * 32;
    int r = lane >> 2, cp = (lane & 3) * 2;
#pragma unroll
    for (int im = 0; im < 2; im++) {
#pragma unroll
        for (int in8 = 0; in8 < 4; in8++) {
            int col = n0w + in8 * 8 + cp;
            float b0 = sbias[col], b1 = sbias[col + 1];
            int m = m0 + m0w + im * 16 + r;
            int t = m & 255, b = m >> 8;
            float* p = Xg + (size_t)t * (BB * LL) + (size_t)b * LL + n0 + col;
            *(float2*)p = make_float2(acc[im][in8][0] + b0, acc[im][in8][1] + b1);
            int m2 = m + 8;
            int t2 = m2 & 255, b2 = m2 >> 8;
            float* p2 = Xg + (size_t)t2 * (BB * LL) + (size_t)b2 * LL + n0 + col;
            *(float2*)p2 = make_float2(acc[im][in8][2] + b0, acc[im][in8][3] + b1);
        }
    }
}

// ================= persistent recurrence (tensor cores) =================
#define PR_AT_HI 0
#define PR_AT_LO 34816
#define PR_WA_HI 69632
#define PR_WA_LO 104448
#define PR_WC_HI 139264
#define PR_WC_LO 157696
#define PR_SMEM  176128

__global__ void __launch_bounds__(512) gru_persistent(
    const float* __restrict__ Wz, const float* __restrict__ Wr,
    const float* __restrict__ Wi, float* __restrict__ out)
{
    extern __shared__ char smb[];
    int tid = threadIdx.x;
    int bx = blockIdx.x;
    unsigned target = 0;

    unsigned atHi = smem_u32(smb + PR_AT_HI), atLo = smem_u32(smb + PR_AT_LO);
    unsigned waHi = smem_u32(smb + PR_WA_HI), waLo = smem_u32(smb + PR_WA_LO);
    unsigned wcHi = smem_u32(smb + PR_WC_HI), wcLo = smem_u32(smb + PR_WC_LO);

    // CTA roles
    int kidxA = bx >> 4;            // 0..7  (phase-A K-slice of 128)
    int n0A   = (bx & 15) * 128;    // over N=2048
    int kidxC = bx >> 3;            // 0..15 (phase-C K-slice of 64)
    int n0C   = (bx & 7) * 128;     // over N=1024

    // element slice owned by this CTA for reduce phases (float2 over [B][L])
    int e2 = bx * 512 + tid;
    int bE = e2 >> 9, l2 = e2 & 511;

    // one-time: weight slices -> smem bf16 hi/lo (reused for all 256 steps)
    {
        const float* wbA = (n0A < 1024) ? Wz + (size_t)n0A * 1536
                                        : Wr + (size_t)(n0A - 1024) * 1536;
        stage_pad<128, ASST>(smb + PR_WA_HI, smb + PR_WA_LO, wbA, 1536, 512 + kidxA * 128);
        stage_pad<64, CSST>(smb + PR_WC_HI, smb + PR_WC_LO,
                            Wi + (size_t)n0C * 1536, 1536, 512 + kidxC * 64);
    }
    // init h split = 0
    ((unsigned*)g_hh)[e2] = 0u;
    ((unsigned*)g_hl)[e2] = 0u;
    target += NB; grid_sync(target);

    for (int t = 0; t < TT; ++t) {
        float z0, z1, h0, h1;   // carried from phase B to phase D in registers

        // ---- Phase A: h @ [Wzh | Wrh]^T partials (K-slice 128) ----
        {
            stage_copy<128>(smb + PR_AT_HI, smb + PR_AT_LO, g_hh, g_hl, kidxA * 128);
            __syncthreads();
            // prefetch phase-B inputs under the GEMM
            float2 pf_xz = ((const float2*)g_xz)[(size_t)t * 65536 + e2];
            float2 pf_xr = ((const float2*)g_xr)[(size_t)t * 65536 + e2];
            unsigned pf_hh = ((const unsigned*)g_hh)[e2];
            unsigned pf_hl = ((const unsigned*)g_hl)[e2];

            float acc[2][4][4];
            zero_acc(acc);
            wgemm<ASST, ASST>(atHi, atLo, waHi, waLo, 8, acc);
            store_acc(g_p1 + (size_t)kidxA * BB * 2048 + n0A, 2048, acc);

            h0 = bf_lo(pf_hh) + bf_lo(pf_hl);
            h1 = bf_hi(pf_hh) + bf_hi(pf_hl);
            z0 = pf_xz.x; z1 = pf_xz.y;     // stash pre-activation in z regs
            // rs pre-activation kept in pf_xr
            target += NB; grid_sync(target);

            // ---- Phase B: reduce1 -> z (regs), rh split (gmem) ----
            const float2* P = (const float2*)g_p1;
            float2 zs = make_float2(z0, z1);
            float2 rs = pf_xr;
#pragma unroll
            for (int k = 0; k < 8; k++) {
                float2 pz = P[(size_t)k * 131072 + bE * 1024 + l2];
                float2 pr = P[(size_t)k * 131072 + bE * 1024 + 512 + l2];
                zs.x += pz.x; zs.y += pz.y;
                rs.x += pr.x; rs.y += pr.y;
            }
            z0 = 1.f / (1.f + __expf(-zs.x));
            z1 = 1.f / (1.f + __expf(-zs.y));
            float r0 = 1.f / (1.f + __expf(-rs.x));
            float r1 = 1.f / (1.f + __expf(-rs.y));
            float rh0 = r0 * h0, rh1 = r1 * h1;
            __nv_bfloat16 bh0 = __float2bfloat16(rh0);
            __nv_bfloat16 bh1 = __float2bfloat16(rh1);
            float rl0 = rh0 - __bfloat162float(bh0);
            float rl1 = rh1 - __bfloat162float(bh1);
            ((unsigned*)g_rhh)[e2] = (unsigned)__bfloat16_as_ushort(bh0) |
                                     ((unsigned)__bfloat16_as_ushort(bh1) << 16);
            ((unsigned*)g_rhl)[e2] = pack_bf2(rl0, rl1);
        }
        target += NB; grid_sync(target);

        // ---- Phase C: (r*h) @ Wih^T partials (K-slice 64) ----
        float2 pf_xi;
        {
            stage_copy<64>(smb + PR_AT_HI, smb + PR_AT_LO, g_rhh, g_rhl, kidxC * 64);
            __syncthreads();
            pf_xi = ((const float2*)g_xi)[(size_t)t * 65536 + e2];   // prefetch for D
            float acc[2][4][4];
            zero_acc(acc);
            wgemm<ASST, CSST>(atHi, atLo, wcHi, wcLo, 4, acc);
            store_acc(g_p2 + (size_t)kidxC * BB * LL + n0C, 1024, acc);
        }
        target += NB; grid_sync(target);

        // ---- Phase D: reduce2 -> h_new, emit history ----
        {
            float2 c = pf_xi;
            const float2* P = (const float2*)g_p2;
#pragma unroll
            for (int k = 0; k < 16; k++) {
                float2 p = P[(size_t)k * 65536 + e2];
                c.x += p.x; c.y += p.y;
            }
            float hn0 = (1.f - z0) * h0 + z0 * tanhf(c.x);
            float hn1 = (1.f - z1) * h1 + z1 * tanhf(c.y);
            ((float2*)out)[(size_t)t * 65536 + e2] = make_float2(hn0, hn1);
            __nv_bfloat16 bh0 = __float2bfloat16(hn0);
            __nv_bfloat16 bh1 = __float2bfloat16(hn1);
            float hl0 = hn0 - __bfloat162float(bh0);
            float hl1 = hn1 - __bfloat162float(bh1);
            ((unsigned*)g_hh)[e2] = (unsigned)__bfloat16_as_ushort(bh0) |
                                    ((unsigned)__bfloat16_as_ushort(bh1) << 16);
            ((unsigned*)g_hl)[e2] = pack_bf2(hl0, hl1);
        }
        target += NB; grid_sync(target);
    }

    // exit protocol: last CTA resets barrier counters
    if (tid == 0) {
        __threadfence();
        unsigned done = atomicAdd(&g_bar2, 1u) + 1;
        if (done == NB) {
            g_bar1 = 0;
            g_bar2 = 0;
            __threadfence();
        }
    }
}

extern "C" void kernel_launch(void* const* d_in, const int* in_sizes, int n_in,
                              void* d_out, int out_size) {
    const float* x  = (const float*)d_in[0];
    const float* Wz = (const float*)d_in[1];
    const float* bz = (const float*)d_in[2];
    const float* Wr = (const float*)d_in[3];
    const float* br = (const float*)d_in[4];
    const float* Wi = (const float*)d_in[5];
    const float* bi = (const float*)d_in[6];
    float* out = (float*)d_out;

    cudaFuncSetAttribute(xproj_kernel, cudaFuncAttributeMaxDynamicSharedMemorySize, XP_SMEM);
    cudaFuncSetAttribute(gru_persistent, cudaFuncAttributeMaxDynamicSharedMemorySize, PR_SMEM);

    xproj_kernel<<<dim3(24, 256), 512, XP_SMEM>>>(x, Wz, bz, Wr, br, Wi, bi);
    gru_persistent<<<NB, 512, PR_SMEM>>>(Wz, Wr, Wi, out);
}

// round 9
// speedup vs baseline: 2.2406x; 1.2155x over previous
#include <cuda_runtime.h>
#include <cuda_fp16.h>
#include <math.h>

#define BB 128
#define TT 256
#define DD 512
#define LL 1024
#define NB 128   // persistent grid size (<=148 SMs -> co-resident)

// ---------- scratch (static device memory; no allocations) ----------
__device__ __align__(16) float g_xz[TT * BB * LL];   // x @ Wz_x^T + bz, [t][b][l]
__device__ __align__(16) float g_xr[TT * BB * LL];
__device__ __align__(16) float g_xi[TT * BB * LL];
__device__ __align__(16) __half g_hf [BB * LL];      // h  (single fp16)
__device__ __align__(16) __half g_rhf[BB * LL];      // r*h (single fp16)
__device__ __align__(16) float g_p1[8  * BB * 2048]; // K-split partials, phase 1
__device__ __align__(16) float g_p2[16 * BB * LL];   // K-split partials, phase 2
__device__ unsigned g_bar1 = 0;
__device__ unsigned g_bar2 = 0;

// ---- software grid barrier (persistent kernel) ----
__device__ __forceinline__ void grid_sync(unsigned target) {
    __syncthreads();
    if (threadIdx.x == 0) {
        __threadfence();
        atomicAdd(&g_bar1, 1u);
        unsigned v;
        do {
            asm volatile("ld.acquire.gpu.u32 %0, [%1];" : "=r"(v) : "l"(&g_bar1));
        } while (v < target);
    }
    __syncthreads();
}

// ---- portable tensor-core primitives ----
__device__ __forceinline__ unsigned smem_u32(const void* p) {
    unsigned a;
    asm("{ .reg .u64 t; cvta.to.shared.u64 t, %1; cvt.u32.u64 %0, t; }" : "=r"(a) : "l"(p));
    return a;
}
__device__ __forceinline__ void ldsm4(unsigned (&r)[4], unsigned addr) {
    asm volatile("ldmatrix.sync.aligned.m8n8.x4.shared.b16 {%0,%1,%2,%3}, [%4];"
                 : "=r"(r[0]), "=r"(r[1]), "=r"(r[2]), "=r"(r[3]) : "r"(addr));
}
__device__ __forceinline__ void mma16816(float (&d)[4], const unsigned (&a)[4],
                                         unsigned b0, unsigned b1) {
    asm volatile("mma.sync.aligned.m16n8k16.row.col.f32.f16.f16.f32 "
                 "{%0,%1,%2,%3}, {%4,%5,%6,%7}, {%8,%9}, {%0,%1,%2,%3};"
                 : "+f"(d[0]), "+f"(d[1]), "+f"(d[2]), "+f"(d[3])
                 : "r"(a[0]), "r"(a[1]), "r"(a[2]), "r"(a[3]), "r"(b0), "r"(b1));
}

// ---- fp16 pack helpers ----
__device__ __forceinline__ unsigned pack_h2(float a, float b) {
    return (unsigned)__half_as_ushort(__float2half_rn(a)) |
           ((unsigned)__half_as_ushort(__float2half_rn(b)) << 16);
}
__device__ __forceinline__ float h2_lo(unsigned u) {
    return __half2float(__ushort_as_half((unsigned short)(u & 0xFFFF)));
}
__device__ __forceinline__ float h2_hi(unsigned u) {
    return __half2float(__ushort_as_half((unsigned short)(u >> 16)));
}

// ---- fp32 -> (fp16 hi, fp16 lo) split-stage into padded-row smem tile ----
// 512 threads, 128 rows, 4 threads per row. Row stride SST fp16 elements.
template<int WIDTH, int SST>
__device__ __forceinline__ void stage_split(char* __restrict__ hiB, char* __restrict__ loB,
                                            const float* __restrict__ src, int srcStride, int c0)
{
    int tid = threadIdx.x;
    int r = tid >> 2, part = tid & 3;
    const int CH = WIDTH / 4;
    int kl0 = part * CH;
    const float* s = src + (size_t)r * srcStride + c0 + kl0;
    unsigned short* hp = (unsigned short*)hiB + r * SST + kl0;
    unsigned short* lp = (unsigned short*)loB + r * SST + kl0;
#pragma unroll
    for (int g = 0; g < CH / 8; g++) {
        float4 f0 = *(const float4*)(s + g * 8);
        float4 f1 = *(const float4*)(s + g * 8 + 4);
        float xs[8] = {f0.x, f0.y, f0.z, f0.w, f1.x, f1.y, f1.z, f1.w};
        unsigned hu[4], lu[4];
#pragma unroll
        for (int p = 0; p < 4; p++) {
            __half h0 = __float2half_rn(xs[2 * p]);
            __half h1 = __float2half_rn(xs[2 * p + 1]);
            float l0 = xs[2 * p]     - __half2float(h0);
            float l1 = xs[2 * p + 1] - __half2float(h1);
            hu[p] = (unsigned)__half_as_ushort(h0) | ((unsigned)__half_as_ushort(h1) << 16);
            lu[p] = pack_h2(l0, l1);
        }
        *(uint4*)(hp + g * 8) = make_uint4(hu[0], hu[1], hu[2], hu[3]);
        *(uint4*)(lp + g * 8) = make_uint4(lu[0], lu[1], lu[2], lu[3]);
    }
}

// ---- fp32 -> single fp16 stage (A operand of xproj) ----
template<int WIDTH, int SST>
__device__ __forceinline__ void stage_single(char* __restrict__ dst,
                                             const float* __restrict__ src, int srcStride, int c0)
{
    int tid = threadIdx.x;
    int r = tid >> 2, part = tid & 3;
    const int CH = WIDTH / 4;
    int kl0 = part * CH;
    const float* s = src + (size_t)r * srcStride + c0 + kl0;
    unsigned short* dp = (unsigned short*)dst + r * SST + kl0;
#pragma unroll
    for (int g = 0; g < CH / 8; g++) {
        float4 f0 = *(const float4*)(s + g * 8);
        float4 f1 = *(const float4*)(s + g * 8 + 4);
        uint4 u;
        u.x = pack_h2(f0.x, f0.y);
        u.y = pack_h2(f0.z, f0.w);
        u.z = pack_h2(f1.x, f1.y);
        u.w = pack_h2(f1.z, f1.w);
        *(uint4*)(dp + g * 8) = u;
    }
}

// ---- pure-copy stage: fp16 gmem array -> padded smem (no conversion) ----
#define ASST 136
#define CSST 72
template<int WIDTH>
__device__ __forceinline__ void stage_copyA(char* __restrict__ dst,
                                            const __half* __restrict__ srcH, int c0)
{
    int tid = threadIdx.x;
    int r = tid >> 2, part = tid & 3;
    const int CH = WIDTH / 4;   // 32 (A) or 16 (C) halfs per thread
    const uint4* sH = (const uint4*)(srcH + (size_t)r * LL + c0 + part * CH);
    uint4* dH = (uint4*)((unsigned short*)dst + r * ASST + part * CH);
#pragma unroll
    for (int i = 0; i < CH / 8; i++) dH[i] = sH[i];
}

// ---- warp-tile GEMM: CTA 128x128, 16 warps as 4(m)x4(n), warp tile 32x32 ----
// A single fp16, B split fp16: 2 terms -> 16 MMAs, 6 ldsm per kstep per warp.
template<int SSTA, int SSTB>
__device__ __forceinline__ void wgemm(unsigned aS, unsigned bHi, unsigned bLo,
                                      int ksteps, float (&acc)[2][4][4])
{
    int lane = threadIdx.x & 31, wid = threadIdx.x >> 5;
    int m0w = (wid & 3) * 32, n0w = (wid >> 2) * 32;
    unsigned aoff = ((m0w + (lane & 15)) * SSTA + ((lane >> 4) << 3)) * 2;
    unsigned boff = ((n0w + (lane & 7) + ((lane >> 4) & 1) * 8) * SSTB
                     + (((lane >> 3) & 1) << 3)) * 2;
    for (int ks = 0; ks < ksteps; ks++) {
        unsigned ka = aoff + ks * 32, kb = boff + ks * 32;
        unsigned bh[2][4], bl[2][4];
        ldsm4(bh[0], bHi + kb);
        ldsm4(bh[1], bHi + kb + 16 * SSTB * 2);
        ldsm4(bl[0], bLo + kb);
        ldsm4(bl[1], bLo + kb + 16 * SSTB * 2);
#pragma unroll
        for (int im = 0; im < 2; im++) {
            unsigned a[4];
            ldsm4(a, aS + ka + im * 16 * SSTA * 2);
#pragma unroll
            for (int ib = 0; ib < 2; ib++) {
                mma16816(acc[im][ib * 2 + 0], a, bh[ib][0], bh[ib][1]);
                mma16816(acc[im][ib * 2 + 1], a, bh[ib][2], bh[ib][3]);
                mma16816(acc[im][ib * 2 + 0], a, bl[ib][0], bl[ib][1]);
                mma16816(acc[im][ib * 2 + 1], a, bl[ib][2], bl[ib][3]);
            }
        }
    }
}

__device__ __forceinline__ void zero_acc(float (&acc)[2][4][4]) {
#pragma unroll
    for (int i = 0; i < 2; i++)
#pragma unroll
        for (int j = 0; j < 4; j++)
#pragma unroll
            for (int q = 0; q < 4; q++) acc[i][j][q] = 0.f;
}

__device__ __forceinline__ void store_acc(float* __restrict__ dst, int ldd,
                                          const float (&acc)[2][4][4])
{
    int lane = threadIdx.x & 31, wid = threadIdx.x >> 5;
    int m0w = (wid & 3) * 32, n0w = (wid >> 2) * 32;
    int r = lane >> 2, cp = (lane & 3) * 2;
#pragma unroll
    for (int im = 0; im < 2; im++)
#pragma unroll
        for (int in8 = 0; in8 < 4; in8++) {
            float* p = dst + (size_t)(m0w + im * 16 + r) * ldd + n0w + in8 * 8 + cp;
            *(float2*)p = make_float2(acc[im][in8][0], acc[im][in8][1]);
            *(float2*)(p + 8 * ldd) = make_float2(acc[im][in8][2], acc[im][in8][3]);
        }
}

// ================= xproj: x @ W_x^T + b, tensor cores =================
#define XSST 72
#define XTB  18432
#define XP_SMEM (3 * XTB)

__global__ void __launch_bounds__(512) xproj_kernel(
    const float* __restrict__ x,
    const float* __restrict__ Wz, const float* __restrict__ bz,
    const float* __restrict__ Wr, const float* __restrict__ br,
    const float* __restrict__ Wi, const float* __restrict__ bi)
{
    extern __shared__ char smb[];
    __shared__ float sbias[128];
    char* AS = smb;
    char* WH = smb + XTB;
    char* WL = smb + 2 * XTB;

    int tid = threadIdx.x;
    int g = blockIdx.x >> 3;
    int n0 = (blockIdx.x & 7) * 128;
    int m0 = blockIdx.y * 128;
    const float* W    = (g == 0) ? Wz : ((g == 1) ? Wr : Wi);
    const float* bias = (g == 0) ? bz : ((g == 1) ? br : bi);
    float* Xg         = (g == 0) ? g_xz : ((g == 1) ? g_xr : g_xi);

    if (tid < 128) sbias[tid] = bias[n0 + tid];

    unsigned aS = smem_u32(AS), bHi = smem_u32(WH), bLo = smem_u32(WL);

    float acc[2][4][4];
    zero_acc(acc);

    for (int c = 0; c < 8; c++) {           // K=512 in 8 chunks of 64
        int k0 = c * 64;
        stage_single<64, XSST>(AS, x + (size_t)m0 * DD, DD, k0);
        stage_split<64, XSST>(WH, WL, W + (size_t)n0 * 1536, 1536, k0);
        __syncthreads();
        wgemm<XSST, XSST>(aS, bHi, bLo, 4, acc);
        __syncthreads();
    }

    int lane = tid & 31, wid = tid >> 5;
    int m0w = (wid & 3) * 32, n0w = (wid >> 2) * 32;
    int r = lane >> 2, cp = (lane & 3) * 2;
#pragma unroll
    for (int im = 0; im < 2; im++) {
#pragma unroll
        for (int in8 = 0; in8 < 4; in8++) {
            int col = n0w + in8 * 8 + cp;
            float b0 = sbias[col], b1 = sbias[col + 1];
            int m = m0 + m0w + im * 16 + r;
            int t = m & 255, b = m >> 8;
            float* p = Xg + (size_t)t * (BB * LL) + (size_t)b * LL + n0 + col;
            *(float2*)p = make_float2(acc[im][in8][0] + b0, acc[im][in8][1] + b1);
            int m2 = m + 8;
            int t2 = m2 & 255, b2 = m2 >> 8;
            float* p2 = Xg + (size_t)t2 * (BB * LL) + (size_t)b2 * LL + n0 + col;
            *(float2*)p2 = make_float2(acc[im][in8][2] + b0, acc[im][in8][3] + b1);
        }
    }
}

// ================= persistent recurrence (tensor cores) =================
// smem (bytes): AT single 128x136 (34816), WA hi/lo 128x136, WC hi/lo 128x72
#define PR_AT    0
#define PR_WA_HI 34816
#define PR_WA_LO 69632
#define PR_WC_HI 104448
#define PR_WC_LO 122880
#define PR_SMEM  141312

__global__ void __launch_bounds__(512) gru_persistent(
    const float* __restrict__ Wz, const float* __restrict__ Wr,
    const float* __restrict__ Wi, float* __restrict__ out)
{
    extern __shared__ char smb[];
    int tid = threadIdx.x;
    int bx = blockIdx.x;
    unsigned target = 0;

    unsigned atS  = smem_u32(smb + PR_AT);
    unsigned waHi = smem_u32(smb + PR_WA_HI), waLo = smem_u32(smb + PR_WA_LO);
    unsigned wcHi = smem_u32(smb + PR_WC_HI), wcLo = smem_u32(smb + PR_WC_LO);

    // CTA roles
    int kidxA = bx >> 4;            // 0..7  (phase-A K-slice of 128)
    int n0A   = (bx & 15) * 128;    // over N=2048
    int kidxC = bx >> 3;            // 0..15 (phase-C K-slice of 64)
    int n0C   = (bx & 7) * 128;     // over N=1024

    // element slice owned by this CTA for reduce phases (float2 over [B][L])
    int e2 = bx * 512 + tid;
    int bE = e2 >> 9, l2 = e2 & 511;

    // one-time: weight slices -> smem fp16 hi/lo (reused for all 256 steps)
    {
        const float* wbA = (n0A < 1024) ? Wz + (size_t)n0A * 1536
                                        : Wr + (size_t)(n0A - 1024) * 1536;
        stage_split<128, ASST>(smb + PR_WA_HI, smb + PR_WA_LO, wbA, 1536, 512 + kidxA * 128);
        stage_split<64, CSST>(smb + PR_WC_HI, smb + PR_WC_LO,
                              Wi + (size_t)n0C * 1536, 1536, 512 + kidxC * 64);
    }
    // init h = 0
    ((unsigned*)g_hf)[e2] = 0u;
    target += NB; grid_sync(target);

    for (int t = 0; t < TT; ++t) {
        float z0, z1, h0, h1;   // carried from phase B to phase D in registers

        // ---- Phase A: h @ [Wzh | Wrh]^T partials (K-slice 128) ----
        {
            stage_copyA<128>(smb + PR_AT, g_hf, kidxA * 128);
            __syncthreads();
            // prefetch phase-B inputs under the GEMM
            float2 pf_xz = ((const float2*)g_xz)[(size_t)t * 65536 + e2];
            float2 pf_xr = ((const float2*)g_xr)[(size_t)t * 65536 + e2];
            unsigned pf_h = ((const unsigned*)g_hf)[e2];

            float acc[2][4][4];
            zero_acc(acc);
            wgemm<ASST, ASST>(atS, waHi, waLo, 8, acc);
            store_acc(g_p1 + (size_t)kidxA * BB * 2048 + n0A, 2048, acc);

            h0 = h2_lo(pf_h);
            h1 = h2_hi(pf_h);
            target += NB; grid_sync(target);

            // ---- Phase B: reduce1 -> z (regs), rh (gmem fp16) ----
            const float2* P = (const float2*)g_p1;
            float2 zs = pf_xz;
            float2 rs = pf_xr;
#pragma unroll
            for (int k = 0; k < 8; k++) {
                float2 pz = P[(size_t)k * 131072 + bE * 1024 + l2];
                float2 pr = P[(size_t)k * 131072 + bE * 1024 + 512 + l2];
                zs.x += pz.x; zs.y += pz.y;
                rs.x += pr.x; rs.y += pr.y;
            }
            z0 = 1.f / (1.f + __expf(-zs.x));
            z1 = 1.f / (1.f + __expf(-zs.y));
            float r0 = 1.f / (1.f + __expf(-rs.x));
            float r1 = 1.f / (1.f + __expf(-rs.y));
            ((unsigned*)g_rhf)[e2] = pack_h2(r0 * h0, r1 * h1);
        }
        target += NB; grid_sync(target);

        // ---- Phase C: (r*h) @ Wih^T partials (K-slice 64) ----
        float2 pf_xi;
        {
            stage_copyA<64>(smb + PR_AT, g_rhf, kidxC * 64);
            __syncthreads();
            pf_xi = ((const float2*)g_xi)[(size_t)t * 65536 + e2];   // prefetch for D
            float acc[2][4][4];
            zero_acc(acc);
            wgemm<ASST, CSST>(atS, wcHi, wcLo, 4, acc);
            store_acc(g_p2 + (size_t)kidxC * BB * LL + n0C, 1024, acc);
        }
        target += NB; grid_sync(target);

        // ---- Phase D: reduce2 -> h_new, emit history ----
        {
            float2 c = pf_xi;
            const float2* P = (const float2*)g_p2;
#pragma unroll
            for (int k = 0; k < 16; k++) {
                float2 p = P[(size_t)k * 65536 + e2];
                c.x += p.x; c.y += p.y;
            }
            float hn0 = (1.f - z0) * h0 + z0 * tanhf(c.x);
            float hn1 = (1.f - z1) * h1 + z1 * tanhf(c.y);
            ((float2*)out)[(size_t)t * 65536 + e2] = make_float2(hn0, hn1);
            ((unsigned*)g_hf)[e2] = pack_h2(hn0, hn1);
        }
        target += NB; grid_sync(target);
    }

    // exit protocol: last CTA resets barrier counters
    if (tid == 0) {
        __threadfence();
        unsigned done = atomicAdd(&g_bar2, 1u) + 1;
        if (done == NB) {
            g_bar1 = 0;
            g_bar2 = 0;
            __threadfence();
        }
    }
}

extern "C" void kernel_launch(void* const* d_in, const int* in_sizes, int n_in,
                              void* d_out, int out_size) {
    const float* x  = (const float*)d_in[0];
    const float* Wz = (const float*)d_in[1];
    const float* bz = (const float*)d_in[2];
    const float* Wr = (const float*)d_in[3];
    const float* br = (const float*)d_in[4];
    const float* Wi = (const float*)d_in[5];
    const float* bi = (const float*)d_in[6];
    float* out = (float*)d_out;

    cudaFuncSetAttribute(xproj_kernel, cudaFuncAttributeMaxDynamicSharedMemorySize, XP_SMEM);
    cudaFuncSetAttribute(gru_persistent, cudaFuncAttributeMaxDynamicSharedMemorySize, PR_SMEM);

    xproj_kernel<<<dim3(24, 256), 512, XP_SMEM>>>(x, Wz, bz, Wr, br, Wi, bi);
    gru_persistent<<<NB, 512, PR_SMEM>>>(Wz, Wr, Wi, out);
}